// round 2
// baseline (speedup 1.0000x reference)
#include <cuda_runtime.h>
#include <math.h>
#include <float.h>
#include <stdint.h>

// Problem dims
#define BB 32
#define TT 100
#define SS 100
#define EE 512
#define HH 1024
#define LL 10
#define VV 32000
#define MM (BB*TT)        // 3200
#define TP (TT+2)         // 102 (left-pad 2)

// ---------------- scratch (static device memory; no allocation) ----------------
__device__ float g_wt[(size_t)LL*2*HH*3*HH];     // conv weights transposed [L][2H][3][H] (251.7MB)
__device__ float g_xpad[BB*TP*HH];               // conv_input, padded layout [B][T+2][H]
__device__ float g_emb[MM*EE];                   // embedded [m][E]
__device__ float g_conved[MM*HH];                // GLU output [m][H]
__device__ float g_cbuf[(size_t)MM*2*HH];        // conv output [m][2H]
__device__ float g_comb[MM*EE];                  // comb / hidden [m][E]
__device__ float g_attenc[MM*EE];                // attention-weighted encoder [m][E]
__device__ float g_att[MM*SS];                   // attention [m][S]

// ---------------- small kernels ----------------

// conv_w [L][2H][H][3] -> g_wt [L][2H][3][H]
__global__ void k_transpose_w(const float* __restrict__ w) {
    size_t idx = (size_t)blockIdx.x * 256 + threadIdx.x;
    const size_t total = (size_t)LL*2*HH*3*HH;
    if (idx >= total) return;
    int h = (int)(idx & (HH-1));
    size_t r = idx >> 10;
    int k = (int)(r % 3);
    size_t lo = r / 3;                       // l*2H + o
    g_wt[idx] = w[lo*3*HH + (size_t)h*3 + k];
}

// zero the 2 pad rows of each batch in g_xpad
__global__ void k_zero_pad() {
    int idx = blockIdx.x * 256 + threadIdx.x;   // 32*2*1024 = 65536
    if (idx >= BB*2*HH) return;
    int b = idx >> 11;
    int r = (idx >> 10) & 1;
    int h = idx & (HH-1);
    g_xpad[(size_t)(b*TP + r)*HH + h] = 0.f;
}

// embedded[m][e] = src_emb[target[m]][e] + pos_emb[t][e]
__global__ void k_embed(const int* __restrict__ target,
                        const float* __restrict__ src_emb,
                        const float* __restrict__ pos_emb) {
    int idx = blockIdx.x * 256 + threadIdx.x;    // 3200*512
    if (idx >= MM*EE) return;
    int m = idx >> 9;
    int e = idx & (EE-1);
    int t = m % TT;
    g_emb[idx] = src_emb[(size_t)target[m]*EE + e] + pos_emb[(size_t)t*EE + e];
}

// conved[m][h] = cbuf[m][h] * sigmoid(cbuf[m][H+h])
__global__ void k_glu() {
    int idx = blockIdx.x * 256 + threadIdx.x;    // 3200*1024
    if (idx >= MM*HH) return;
    int m = idx >> 10;
    int h = idx & (HH-1);
    float a = g_cbuf[(size_t)m*2*HH + h];
    float g = g_cbuf[(size_t)m*2*HH + HH + h];
    g_conved[idx] = a / (1.f + expf(-g));
}

// conv_input = (conved + conv_input) * sqrt(0.5), in padded layout
__global__ void k_resid() {
    int idx = blockIdx.x * 256 + threadIdx.x;    // 3200*1024
    if (idx >= MM*HH) return;
    int m = idx >> 10;
    int h = idx & (HH-1);
    int b = m / TT, t = m - b*TT;
    size_t p = (size_t)(b*TP + t + 2)*HH + h;
    g_xpad[p] = (g_conved[idx] + g_xpad[p]) * 0.7071067811865476f;
}

// fused energy + softmax: one block per (b,t) row
__global__ __launch_bounds__(128) void k_energy_softmax(const float* __restrict__ encC) {
    int m = blockIdx.x;
    int b = m / TT;
    __shared__ __align__(16) float sc[EE];
    __shared__ float red[4];
    int tid = threadIdx.x;
    #pragma unroll
    for (int i = tid; i < EE; i += 128) sc[i] = g_comb[(size_t)m*EE + i];
    __syncthreads();
    float val = -FLT_MAX;
    if (tid < SS) {
        const float4* ec = (const float4*)(encC + (size_t)(b*SS + tid)*EE);
        const float4* c4 = (const float4*)sc;
        float acc = 0.f;
        #pragma unroll 8
        for (int i = 0; i < EE/4; i++) {
            float4 e4 = ec[i], cc = c4[i];
            acc += e4.x*cc.x + e4.y*cc.y + e4.z*cc.z + e4.w*cc.w;
        }
        val = acc;
    }
    // block max
    float mx = val;
    #pragma unroll
    for (int o = 16; o > 0; o >>= 1) mx = fmaxf(mx, __shfl_xor_sync(0xffffffffu, mx, o));
    if ((tid & 31) == 0) red[tid >> 5] = mx;
    __syncthreads();
    mx = fmaxf(fmaxf(red[0], red[1]), fmaxf(red[2], red[3]));
    __syncthreads();
    float ex = (tid < SS) ? expf(val - mx) : 0.f;
    float sm = ex;
    #pragma unroll
    for (int o = 16; o > 0; o >>= 1) sm += __shfl_xor_sync(0xffffffffu, sm, o);
    if ((tid & 31) == 0) red[tid >> 5] = sm;
    __syncthreads();
    sm = red[0] + red[1] + red[2] + red[3];
    if (tid < SS) g_att[(size_t)m*SS + tid] = ex / sm;
}

// att_enc[m][e] = sum_s att[m][s] * encComb[b][s][e]
__global__ __launch_bounds__(128) void k_attenc(const float* __restrict__ encComb) {
    int m = blockIdx.x;
    int b = m / TT;
    __shared__ float sa[SS];
    int tid = threadIdx.x;
    if (tid < SS) sa[tid] = g_att[(size_t)m*SS + tid];
    __syncthreads();
    float4 acc = {0.f, 0.f, 0.f, 0.f};
    const float4* base = (const float4*)(encComb + (size_t)b*SS*EE);
    #pragma unroll 4
    for (int s = 0; s < SS; s++) {
        float a = sa[s];
        float4 v = base[s*(EE/4) + tid];
        acc.x += a*v.x; acc.y += a*v.y; acc.z += a*v.z; acc.w += a*v.w;
    }
    ((float4*)(g_attenc + (size_t)m*EE))[tid] = acc;
}

__global__ void k_attcopy(float* __restrict__ dst) {
    int idx = blockIdx.x * 256 + threadIdx.x;
    if (idx < MM*SS) dst[idx] = g_att[idx];
}

// ---------------- generic NT GEMM: C[m,n] = scale*(sum_k A[m,k]*W[n,k] + bias[n] + add[m,n]) ----------------
// amode: 0 identity row, 1 padded(+2) row (for [B,T+2,H] buffers), 2 conv row (no +2; reads 3 overlapping rows)
// cmode: 0 identity, 1 padded(+2)
__global__ __launch_bounds__(256, 2) void gemm_nt(
    const float* __restrict__ A, int amode, int lda,
    const float* __restrict__ W,
    const float* __restrict__ bias,
    const float* __restrict__ add, int ldadd,
    float scale,
    float* __restrict__ C, int cmode, int ldc,
    int M, int N, int K)
{
    __shared__ __align__(16) float As[16][132];
    __shared__ __align__(16) float Bs[16][132];
    const int tid = threadIdx.x;
    const int m0 = blockIdx.y * 128, n0 = blockIdx.x * 128;
    const int tr = tid >> 4, tc = tid & 15;

    size_t aoff[2], woff[2];
    int k4v[2], mls[2];
    #pragma unroll
    for (int it = 0; it < 2; it++) {
        int lin = tid + it * 256;
        int ml = lin >> 2;
        mls[it] = ml;
        k4v[it] = (lin & 3) * 4;
        int m = m0 + ml;
        int rm;
        if (amode == 0) rm = m;
        else { int b = m / TT, t = m - b*TT; rm = b*TP + t + ((amode == 1) ? 2 : 0); }
        aoff[it] = (size_t)rm * lda;
        woff[it] = (size_t)(n0 + ml) * K;
    }

    float acc[8][8];
    #pragma unroll
    for (int i = 0; i < 8; i++)
        #pragma unroll
        for (int j = 0; j < 8; j++) acc[i][j] = 0.f;

    for (int k0 = 0; k0 < K; k0 += 16) {
        #pragma unroll
        for (int it = 0; it < 2; it++) {
            float4 v = *(const float4*)(A + aoff[it] + k0 + k4v[it]);
            int ml = mls[it];
            int kb = k4v[it];
            As[kb+0][ml] = v.x; As[kb+1][ml] = v.y; As[kb+2][ml] = v.z; As[kb+3][ml] = v.w;
            float4 w4 = *(const float4*)(W + woff[it] + k0 + k4v[it]);
            Bs[kb+0][ml] = w4.x; Bs[kb+1][ml] = w4.y; Bs[kb+2][ml] = w4.z; Bs[kb+3][ml] = w4.w;
        }
        __syncthreads();
        #pragma unroll
        for (int kk = 0; kk < 16; kk++) {
            float4 a0 = *(const float4*)&As[kk][tr*8];
            float4 a1 = *(const float4*)&As[kk][tr*8+4];
            float4 b0 = *(const float4*)&Bs[kk][tc*8];
            float4 b1 = *(const float4*)&Bs[kk][tc*8+4];
            float av[8] = {a0.x,a0.y,a0.z,a0.w,a1.x,a1.y,a1.z,a1.w};
            float bv[8] = {b0.x,b0.y,b0.z,b0.w,b1.x,b1.y,b1.z,b1.w};
            #pragma unroll
            for (int i = 0; i < 8; i++)
                #pragma unroll
                for (int j = 0; j < 8; j++)
                    acc[i][j] += av[i]*bv[j];
        }
        __syncthreads();
    }

    #pragma unroll
    for (int i = 0; i < 8; i++) {
        int m = m0 + tr*8 + i;
        if (m >= M) continue;
        int rm = m;
        if (cmode == 1) { int b = m / TT, t = m - b*TT; rm = b*TP + t + 2; }
        size_t crow = (size_t)rm * ldc;
        size_t arow = (size_t)m * ldadd;
        #pragma unroll
        for (int j = 0; j < 8; j++) {
            int n = n0 + tc*8 + j;
            if (n >= N) continue;
            float v = acc[i][j];
            if (bias) v += bias[n];
            if (add)  v += add[arow + n];
            C[crow + n] = v * scale;
        }
    }
}

static void launch_gemm(const float* A, int amode, int lda,
                        const float* W, const float* bias,
                        const float* add, int ldadd, float scale,
                        float* C, int cmode, int ldc,
                        int M, int N, int K) {
    dim3 g((N + 127) / 128, (M + 127) / 128);
    gemm_nt<<<g, 256>>>(A, amode, lda, W, bias, add, ldadd, scale, C, cmode, ldc, M, N, K);
}

// ---------------- launch ----------------
extern "C" void kernel_launch(void* const* d_in, const int* in_sizes, int n_in,
                              void* d_out, int out_size) {
    const int*   target   = (const int*)  d_in[0];
    const float* encC     = (const float*)d_in[1];
    const float* encComb  = (const float*)d_in[2];
    const float* src_emb  = (const float*)d_in[3];
    const float* pos_emb  = (const float*)d_in[4];
    const float* w_eh     = (const float*)d_in[5];
    const float* b_eh     = (const float*)d_in[6];
    const float* w_he     = (const float*)d_in[7];
    const float* b_he     = (const float*)d_in[8];
    const float* w_ahe    = (const float*)d_in[9];
    const float* b_ahe    = (const float*)d_in[10];
    const float* w_aeh    = (const float*)d_in[11];
    const float* b_aeh    = (const float*)d_in[12];
    const float* w_fc     = (const float*)d_in[13];
    const float* b_fc     = (const float*)d_in[14];
    const float* conv_w   = (const float*)d_in[15];
    const float* conv_b   = (const float*)d_in[16];
    float* out = (float*)d_out;

    float *p_wt, *p_xpad, *p_emb, *p_conved, *p_cbuf, *p_comb, *p_attenc;
    cudaGetSymbolAddress((void**)&p_wt, g_wt);
    cudaGetSymbolAddress((void**)&p_xpad, g_xpad);
    cudaGetSymbolAddress((void**)&p_emb, g_emb);
    cudaGetSymbolAddress((void**)&p_conved, g_conved);
    cudaGetSymbolAddress((void**)&p_cbuf, g_cbuf);
    cudaGetSymbolAddress((void**)&p_comb, g_comb);
    cudaGetSymbolAddress((void**)&p_attenc, g_attenc);

    const float SC = 0.7071067811865476f;
    const size_t WT_TOTAL = (size_t)LL*2*HH*3*HH;

    k_transpose_w<<<(unsigned)((WT_TOTAL + 255) / 256), 256>>>(conv_w);
    k_zero_pad<<<(BB*2*HH + 255) / 256, 256>>>();
    k_embed<<<(MM*EE + 255) / 256, 256>>>(target, src_emb, pos_emb);

    // conv_input = embedded @ w_eh^T + b_eh  -> padded buffer
    launch_gemm(p_emb, 0, EE, w_eh, b_eh, nullptr, 0, 1.f, p_xpad, 1, HH, MM, HH, EE);

    for (int l = 0; l < LL; l++) {
        // causal conv as one GEMM: K = 3*H contiguous in padded buffer
        launch_gemm(p_xpad, 2, HH, p_wt + (size_t)l*2*HH*3*HH, conv_b + (size_t)l*2*HH,
                    nullptr, 0, 1.f, p_cbuf, 0, 2*HH, MM, 2*HH, 3*HH);
        k_glu<<<(MM*HH + 255) / 256, 256>>>();
        // comb = (conved @ w_ahe^T + b_ahe + embedded) * sqrt(.5)
        launch_gemm(p_conved, 0, HH, w_ahe, b_ahe, p_emb, EE, SC, p_comb, 0, EE, MM, EE, HH);
        k_energy_softmax<<<MM, 128>>>(encC);
        k_attenc<<<MM, 128>>>(encComb);
        // conved = (conved + att_enc @ w_aeh^T + b_aeh) * sqrt(.5)   (in place via add)
        launch_gemm(p_attenc, 0, EE, w_aeh, b_aeh, p_conved, HH, SC, p_conved, 0, HH, MM, HH, EE);
        // conv_input = (conved + conv_input) * sqrt(.5)
        k_resid<<<(MM*HH + 255) / 256, 256>>>();
    }

    // hidden = conv_input @ w_he^T + b_he
    launch_gemm(p_xpad, 1, HH, w_he, b_he, nullptr, 0, 1.f, p_comb, 0, EE, MM, EE, HH);
    // logits = hidden @ w_fc^T + b_fc  -> d_out
    launch_gemm(p_comb, 0, EE, w_fc, b_fc, nullptr, 0, 1.f, out, 0, VV, MM, VV, EE);

    // attention (last layer) appended after logits
    const long long ATT_OFF = (long long)MM * VV;   // 102,400,000
    if ((long long)out_size >= ATT_OFF + (long long)MM*SS) {
        k_attcopy<<<(MM*SS + 255) / 256, 256>>>(out + ATT_OFF);
    }
}

// round 5
// speedup vs baseline: 2.1188x; 2.1188x over previous
#include <cuda_runtime.h>
#include <cuda_bf16.h>
#include <math.h>
#include <float.h>
#include <stdint.h>

// Problem dims
#define BB 32
#define TT 100
#define SS 100
#define EE 512
#define HH 1024
#define LL 10
#define VV 32000
#define MM (BB*TT)        // 3200
#define TP (TT+2)         // 102 (left-pad 2)

typedef __nv_bfloat16 bf16;

// ---------------- scratch (static device memory; no allocation) ----------------
// fp32 buffers
__device__ float g_xpad[(size_t)BB*TP*HH];       // conv_input, padded [B][T+2][H]
__device__ float g_emb[(size_t)MM*EE];           // embedded
__device__ float g_conved[(size_t)MM*HH];        // GLU output
__device__ float g_cbuf[(size_t)MM*2*HH];        // conv output [m][2H]
__device__ float g_comb[(size_t)MM*EE];          // comb / hidden
__device__ float g_att[(size_t)MM*SS];           // attention

// bf16 hi/lo pairs (split precision for tensor-core GEMM)
__device__ bf16 g_wt_h[(size_t)LL*2*HH*3*HH], g_wt_l[(size_t)LL*2*HH*3*HH];
__device__ bf16 g_weh_h[(size_t)HH*EE],  g_weh_l[(size_t)HH*EE];
__device__ bf16 g_whe_h[(size_t)EE*HH],  g_whe_l[(size_t)EE*HH];
__device__ bf16 g_wahe_h[(size_t)EE*HH], g_wahe_l[(size_t)EE*HH];
__device__ bf16 g_waeh_h[(size_t)HH*EE], g_waeh_l[(size_t)HH*EE];
__device__ bf16 g_wfc_h[(size_t)VV*EE],  g_wfc_l[(size_t)VV*EE];
__device__ bf16 g_xpad_h[(size_t)BB*TP*HH], g_xpad_l[(size_t)BB*TP*HH];
__device__ bf16 g_emb_h[(size_t)MM*EE],     g_emb_l[(size_t)MM*EE];
__device__ bf16 g_conved_h[(size_t)MM*HH],  g_conved_l[(size_t)MM*HH];
__device__ bf16 g_attenc_h[(size_t)MM*EE],  g_attenc_l[(size_t)MM*EE];
__device__ bf16 g_comb_h[(size_t)MM*EE],    g_comb_l[(size_t)MM*EE];

__device__ __forceinline__ void splitf(float v, bf16& h, bf16& l) {
    bf16 hh = __float2bfloat16(v);
    h = hh;
    l = __float2bfloat16(v - __bfloat162float(hh));
}

// ---------------- small kernels ----------------

// conv_w [L][2H][H][3] -> wt [L][2H][3][H] (hi/lo split)
__global__ void k_transpose_w(const float* __restrict__ w) {
    size_t idx = (size_t)blockIdx.x * 256 + threadIdx.x;
    const size_t total = (size_t)LL*2*HH*3*HH;
    if (idx >= total) return;
    int h = (int)(idx & (HH-1));
    size_t r = idx >> 10;
    int k = (int)(r % 3);
    size_t lo = r / 3;                       // l*2H + o
    float v = w[lo*3*HH + (size_t)h*3 + k];
    splitf(v, g_wt_h[idx], g_wt_l[idx]);
}

// generic fp32 -> hi/lo split
__global__ void k_split(const float* __restrict__ src, bf16* __restrict__ h,
                        bf16* __restrict__ l, size_t n) {
    size_t idx = (size_t)blockIdx.x * 256 + threadIdx.x;
    if (idx >= n) return;
    splitf(src[idx], h[idx], l[idx]);
}

// zero pad rows of xpad (fp32 + hi/lo)
__global__ void k_zero_pad() {
    int idx = blockIdx.x * 256 + threadIdx.x;   // 32*2*1024
    if (idx >= BB*2*HH) return;
    int b = idx >> 11;
    int r = (idx >> 10) & 1;
    int h = idx & (HH-1);
    size_t p = (size_t)(b*TP + r)*HH + h;
    g_xpad[p] = 0.f;
    g_xpad_h[p] = __float2bfloat16(0.f);
    g_xpad_l[p] = __float2bfloat16(0.f);
}

__global__ void k_embed(const int* __restrict__ target,
                        const float* __restrict__ src_emb,
                        const float* __restrict__ pos_emb) {
    int idx = blockIdx.x * 256 + threadIdx.x;    // 3200*512
    if (idx >= MM*EE) return;
    int m = idx >> 9;
    int e = idx & (EE-1);
    int t = m % TT;
    float v = src_emb[(size_t)target[m]*EE + e] + pos_emb[(size_t)t*EE + e];
    g_emb[idx] = v;
    splitf(v, g_emb_h[idx], g_emb_l[idx]);
}

__global__ void k_glu() {
    int idx = blockIdx.x * 256 + threadIdx.x;    // 3200*1024
    if (idx >= MM*HH) return;
    int m = idx >> 10;
    int h = idx & (HH-1);
    float a = g_cbuf[(size_t)m*2*HH + h];
    float g = g_cbuf[(size_t)m*2*HH + HH + h];
    float v = a / (1.f + expf(-g));
    g_conved[idx] = v;
    splitf(v, g_conved_h[idx], g_conved_l[idx]);
}

// conv_input = (conved + conv_input) * sqrt(0.5), fused split
__global__ void k_resid() {
    int idx = blockIdx.x * 256 + threadIdx.x;    // 3200*1024
    if (idx >= MM*HH) return;
    int m = idx >> 10;
    int h = idx & (HH-1);
    int b = m / TT, t = m - b*TT;
    size_t p = (size_t)(b*TP + t + 2)*HH + h;
    float v = (g_conved[idx] + g_xpad[p]) * 0.7071067811865476f;
    g_xpad[p] = v;
    splitf(v, g_xpad_h[p], g_xpad_l[p]);
}

// fused energy + softmax
__global__ __launch_bounds__(128) void k_energy_softmax(const float* __restrict__ encC) {
    int m = blockIdx.x;
    int b = m / TT;
    __shared__ __align__(16) float sc[EE];
    __shared__ float red[4];
    int tid = threadIdx.x;
    #pragma unroll
    for (int i = tid; i < EE; i += 128) sc[i] = g_comb[(size_t)m*EE + i];
    __syncthreads();
    float val = -FLT_MAX;
    if (tid < SS) {
        const float4* ec = (const float4*)(encC + (size_t)(b*SS + tid)*EE);
        const float4* c4 = (const float4*)sc;
        float acc = 0.f;
        #pragma unroll 8
        for (int i = 0; i < EE/4; i++) {
            float4 e4 = ec[i], cc = c4[i];
            acc += e4.x*cc.x + e4.y*cc.y + e4.z*cc.z + e4.w*cc.w;
        }
        val = acc;
    }
    float mx = val;
    #pragma unroll
    for (int o = 16; o > 0; o >>= 1) mx = fmaxf(mx, __shfl_xor_sync(0xffffffffu, mx, o));
    if ((tid & 31) == 0) red[tid >> 5] = mx;
    __syncthreads();
    mx = fmaxf(fmaxf(red[0], red[1]), fmaxf(red[2], red[3]));
    __syncthreads();
    float ex = (tid < SS) ? expf(val - mx) : 0.f;
    float sm = ex;
    #pragma unroll
    for (int o = 16; o > 0; o >>= 1) sm += __shfl_xor_sync(0xffffffffu, sm, o);
    if ((tid & 31) == 0) red[tid >> 5] = sm;
    __syncthreads();
    sm = red[0] + red[1] + red[2] + red[3];
    if (tid < SS) g_att[(size_t)m*SS + tid] = ex / sm;
}

// att_enc (writes hi/lo only; used solely as GEMM A)
__global__ __launch_bounds__(128) void k_attenc(const float* __restrict__ encComb) {
    int m = blockIdx.x;
    int b = m / TT;
    __shared__ float sa[SS];
    int tid = threadIdx.x;
    if (tid < SS) sa[tid] = g_att[(size_t)m*SS + tid];
    __syncthreads();
    float4 acc = {0.f, 0.f, 0.f, 0.f};
    const float4* base = (const float4*)(encComb + (size_t)b*SS*EE);
    #pragma unroll 4
    for (int s = 0; s < SS; s++) {
        float a = sa[s];
        float4 v = base[s*(EE/4) + tid];
        acc.x += a*v.x; acc.y += a*v.y; acc.z += a*v.z; acc.w += a*v.w;
    }
    size_t o = (size_t)m*EE + tid*4;
    splitf(acc.x, g_attenc_h[o+0], g_attenc_l[o+0]);
    splitf(acc.y, g_attenc_h[o+1], g_attenc_l[o+1]);
    splitf(acc.z, g_attenc_h[o+2], g_attenc_l[o+2]);
    splitf(acc.w, g_attenc_h[o+3], g_attenc_l[o+3]);
}

__global__ void k_attcopy(float* __restrict__ dst) {
    int idx = blockIdx.x * 256 + threadIdx.x;
    if (idx < MM*SS) dst[idx] = g_att[idx];
}

// ---------------- tensor-core GEMM (bf16x3 split, mma.sync m16n8k16) ----------------
// C[m,n] = scale * (sum_k A[m,k]*W[n,k] + bias[n] + add[m,n])
// A given as hi/lo bf16, W as hi/lo bf16. All dims multiples of 128 (K mult of 32).
// amode: 0 identity row, 1 padded(+2) row, 2 conv row (padded, no +2, K spans 3 rows)

#define KT 32
#define SSTR 40                  // smem row stride in bf16 (conflict-free LDSM)
#define ARR_SZ (128*SSTR)        // 5120 elems
#define BUF_SZ (4*ARR_SZ)        // 20480 elems per stage
#define GSMEM (2*BUF_SZ*2)       // 81920 bytes (double buffered)

__device__ __forceinline__ void ldsm4(uint32_t r[4], unsigned addr) {
    asm volatile("ldmatrix.sync.aligned.m8n8.x4.shared.b16 {%0,%1,%2,%3}, [%4];\n"
        : "=r"(r[0]), "=r"(r[1]), "=r"(r[2]), "=r"(r[3]) : "r"(addr));
}
__device__ __forceinline__ void mma16816(float c[4], const uint32_t a[4],
                                         uint32_t b0, uint32_t b1) {
    asm volatile(
        "mma.sync.aligned.m16n8k16.row.col.f32.bf16.bf16.f32 "
        "{%0,%1,%2,%3},{%4,%5,%6,%7},{%8,%9},{%0,%1,%2,%3};\n"
        : "+f"(c[0]), "+f"(c[1]), "+f"(c[2]), "+f"(c[3])
        : "r"(a[0]), "r"(a[1]), "r"(a[2]), "r"(a[3]), "r"(b0), "r"(b1));
}

__global__ __launch_bounds__(256) void gemm_tc(
    const bf16* __restrict__ Ah, const bf16* __restrict__ Al, int amode, int lda,
    const bf16* __restrict__ Wh, const bf16* __restrict__ Wl,
    const float* __restrict__ bias, const float* __restrict__ add, int ldadd,
    float scale, float* __restrict__ C, int cmode, int ldc, int K)
{
    extern __shared__ bf16 sm[];
    const int tid = threadIdx.x;
    const int lane = tid & 31, warp = tid >> 5;
    const int m0 = blockIdx.y * 128, n0 = blockIdx.x * 128;

    // fill descriptors: 2 iterations x (row, 8-elem chunk) per array
    size_t aoff[2], woff[2];
    int sdst[2];
    #pragma unroll
    for (int it = 0; it < 2; it++) {
        int seg = tid + it * 256;
        int row = seg >> 2, kq = (seg & 3) * 8;
        int m = m0 + row;
        int rm = m;
        if (amode) { int b = m / TT, t = m - b*TT; rm = b*TP + t + ((amode == 1) ? 2 : 0); }
        aoff[it] = (size_t)rm * lda + kq;
        woff[it] = (size_t)(n0 + row) * K + kq;
        sdst[it] = row * SSTR + kq;
    }

    const unsigned sbase = (unsigned)__cvta_generic_to_shared(sm);
    const int mb = (warp & 3) * 32;        // warp m-offset within CTA tile
    const int nb = (warp >> 2) * 64;       // warp n-offset
    const unsigned a_ln = (unsigned)(((lane & 15)*SSTR + (lane >> 4)*8) * 2);
    const unsigned b_ln = (unsigned)((((lane & 7) + ((lane >> 4) << 3))*SSTR
                                     + ((lane >> 3) & 1)*8) * 2);

    float acc[2][8][4];
    #pragma unroll
    for (int i = 0; i < 2; i++)
        #pragma unroll
        for (int j = 0; j < 8; j++)
            #pragma unroll
            for (int q = 0; q < 4; q++) acc[i][j][q] = 0.f;

    uint4 rah[2], ral[2], rbh[2], rbl[2];
    // prologue: load stage 0
    #pragma unroll
    for (int it = 0; it < 2; it++) {
        rah[it] = *(const uint4*)(Ah + aoff[it]);
        ral[it] = *(const uint4*)(Al + aoff[it]);
        rbh[it] = *(const uint4*)(Wh + woff[it]);
        rbl[it] = *(const uint4*)(Wl + woff[it]);
    }
    #pragma unroll
    for (int it = 0; it < 2; it++) {
        *(uint4*)(sm + 0*ARR_SZ + sdst[it]) = rah[it];
        *(uint4*)(sm + 1*ARR_SZ + sdst[it]) = ral[it];
        *(uint4*)(sm + 2*ARR_SZ + sdst[it]) = rbh[it];
        *(uint4*)(sm + 3*ARR_SZ + sdst[it]) = rbl[it];
    }
    __syncthreads();

    const int nK = K / KT;
    for (int s = 0; s < nK; s++) {
        if (s + 1 < nK) {
            int k0 = (s + 1) * KT;
            #pragma unroll
            for (int it = 0; it < 2; it++) {
                rah[it] = *(const uint4*)(Ah + aoff[it] + k0);
                ral[it] = *(const uint4*)(Al + aoff[it] + k0);
                rbh[it] = *(const uint4*)(Wh + woff[it] + k0);
                rbl[it] = *(const uint4*)(Wl + woff[it] + k0);
            }
        }
        // compute on buffer s&1
        unsigned bufb = sbase + (unsigned)((s & 1) * BUF_SZ * 2);
        #pragma unroll
        for (int kk = 0; kk < 2; kk++) {
            unsigned kof = kk * 32;   // 16 bf16 = 32 bytes
            uint32_t ah[2][4], al[2][4], bb[4][4];
            unsigned aH = bufb + (0*ARR_SZ)*2 + a_ln + kof;
            unsigned aL = bufb + (1*ARR_SZ)*2 + a_ln + kof;
            unsigned aB = bufb + (2*ARR_SZ)*2 + b_ln + kof;
            ldsm4(ah[0], aH + (unsigned)((mb + 0)  * (SSTR*2)));
            ldsm4(ah[1], aH + (unsigned)((mb + 16) * (SSTR*2)));
            ldsm4(al[0], aL + (unsigned)((mb + 0)  * (SSTR*2)));
            ldsm4(al[1], aL + (unsigned)((mb + 16) * (SSTR*2)));
            #pragma unroll
            for (int tb = 0; tb < 4; tb++)
                ldsm4(bb[tb], aB + (unsigned)((nb + tb*16) * (SSTR*2)));
            // hi*hi
            #pragma unroll
            for (int tm = 0; tm < 2; tm++)
                #pragma unroll
                for (int j = 0; j < 8; j++)
                    mma16816(acc[tm][j], ah[tm], bb[j>>1][(j&1)*2], bb[j>>1][(j&1)*2+1]);
            // lo*hi
            #pragma unroll
            for (int tm = 0; tm < 2; tm++)
                #pragma unroll
                for (int j = 0; j < 8; j++)
                    mma16816(acc[tm][j], al[tm], bb[j>>1][(j&1)*2], bb[j>>1][(j&1)*2+1]);
            // reload B_lo over bb
            unsigned aBL = bufb + (3*ARR_SZ)*2 + b_ln + kof;
            #pragma unroll
            for (int tb = 0; tb < 4; tb++)
                ldsm4(bb[tb], aBL + (unsigned)((nb + tb*16) * (SSTR*2)));
            // hi*lo
            #pragma unroll
            for (int tm = 0; tm < 2; tm++)
                #pragma unroll
                for (int j = 0; j < 8; j++)
                    mma16816(acc[tm][j], ah[tm], bb[j>>1][(j&1)*2], bb[j>>1][(j&1)*2+1]);
        }
        if (s + 1 < nK) {
            bf16* dst = sm + ((s + 1) & 1) * BUF_SZ;
            #pragma unroll
            for (int it = 0; it < 2; it++) {
                *(uint4*)(dst + 0*ARR_SZ + sdst[it]) = rah[it];
                *(uint4*)(dst + 1*ARR_SZ + sdst[it]) = ral[it];
                *(uint4*)(dst + 2*ARR_SZ + sdst[it]) = rbh[it];
                *(uint4*)(dst + 3*ARR_SZ + sdst[it]) = rbl[it];
            }
        }
        __syncthreads();
    }

    // epilogue
    #pragma unroll
    for (int tm = 0; tm < 2; tm++) {
        #pragma unroll
        for (int half = 0; half < 2; half++) {
            int m = m0 + mb + tm*16 + (lane >> 2) + half*8;
            int rm = m;
            if (cmode == 1) { int b = m / TT, t = m - b*TT; rm = b*TP + t + 2; }
            size_t crow = (size_t)rm * ldc;
            size_t arow = (size_t)m * ldadd;
            #pragma unroll
            for (int j = 0; j < 8; j++) {
                int n = n0 + nb + j*8 + (lane & 3)*2;
                float v0 = acc[tm][j][half*2 + 0];
                float v1 = acc[tm][j][half*2 + 1];
                if (bias) { v0 += bias[n]; v1 += bias[n+1]; }
                if (add)  { v0 += add[arow + n]; v1 += add[arow + n + 1]; }
                float2 r; r.x = v0 * scale; r.y = v1 * scale;
                *(float2*)(C + crow + n) = r;
            }
        }
    }
}

static void launch_tc(const bf16* Ah, const bf16* Al, int amode, int lda,
                      const bf16* Wh, const bf16* Wl,
                      const float* bias, const float* add, int ldadd, float scale,
                      float* C, int cmode, int ldc, int M, int N, int K) {
    dim3 g(N / 128, M / 128);
    gemm_tc<<<g, 256, GSMEM>>>(Ah, Al, amode, lda, Wh, Wl, bias, add, ldadd,
                               scale, C, cmode, ldc, K);
}

// ---------------- launch ----------------
extern "C" void kernel_launch(void* const* d_in, const int* in_sizes, int n_in,
                              void* d_out, int out_size) {
    const int*   target   = (const int*)  d_in[0];
    const float* encC     = (const float*)d_in[1];
    const float* encComb  = (const float*)d_in[2];
    const float* src_emb  = (const float*)d_in[3];
    const float* pos_emb  = (const float*)d_in[4];
    const float* w_eh     = (const float*)d_in[5];
    const float* b_eh     = (const float*)d_in[6];
    const float* w_he     = (const float*)d_in[7];
    const float* b_he     = (const float*)d_in[8];
    const float* w_ahe    = (const float*)d_in[9];
    const float* b_ahe    = (const float*)d_in[10];
    const float* w_aeh    = (const float*)d_in[11];
    const float* b_aeh    = (const float*)d_in[12];
    const float* w_fc     = (const float*)d_in[13];
    const float* b_fc     = (const float*)d_in[14];
    const float* conv_w   = (const float*)d_in[15];
    const float* conv_b   = (const float*)d_in[16];
    float* out = (float*)d_out;

    cudaFuncSetAttribute(gemm_tc, cudaFuncAttributeMaxDynamicSharedMemorySize, GSMEM);

    // device pointers to scratch
    float *p_xpad, *p_emb, *p_conved, *p_cbuf, *p_comb;
    bf16 *p_wt_h, *p_wt_l, *p_weh_h, *p_weh_l, *p_whe_h, *p_whe_l;
    bf16 *p_wahe_h, *p_wahe_l, *p_waeh_h, *p_waeh_l, *p_wfc_h, *p_wfc_l;
    bf16 *p_xpad_h, *p_xpad_l, *p_emb_h, *p_emb_l, *p_conved_h, *p_conved_l;
    bf16 *p_attenc_h, *p_attenc_l, *p_comb_h, *p_comb_l;
    cudaGetSymbolAddress((void**)&p_xpad, g_xpad);
    cudaGetSymbolAddress((void**)&p_emb, g_emb);
    cudaGetSymbolAddress((void**)&p_conved, g_conved);
    cudaGetSymbolAddress((void**)&p_cbuf, g_cbuf);
    cudaGetSymbolAddress((void**)&p_comb, g_comb);
    cudaGetSymbolAddress((void**)&p_wt_h, g_wt_h);   cudaGetSymbolAddress((void**)&p_wt_l, g_wt_l);
    cudaGetSymbolAddress((void**)&p_weh_h, g_weh_h); cudaGetSymbolAddress((void**)&p_weh_l, g_weh_l);
    cudaGetSymbolAddress((void**)&p_whe_h, g_whe_h); cudaGetSymbolAddress((void**)&p_whe_l, g_whe_l);
    cudaGetSymbolAddress((void**)&p_wahe_h, g_wahe_h); cudaGetSymbolAddress((void**)&p_wahe_l, g_wahe_l);
    cudaGetSymbolAddress((void**)&p_waeh_h, g_waeh_h); cudaGetSymbolAddress((void**)&p_waeh_l, g_waeh_l);
    cudaGetSymbolAddress((void**)&p_wfc_h, g_wfc_h); cudaGetSymbolAddress((void**)&p_wfc_l, g_wfc_l);
    cudaGetSymbolAddress((void**)&p_xpad_h, g_xpad_h); cudaGetSymbolAddress((void**)&p_xpad_l, g_xpad_l);
    cudaGetSymbolAddress((void**)&p_emb_h, g_emb_h); cudaGetSymbolAddress((void**)&p_emb_l, g_emb_l);
    cudaGetSymbolAddress((void**)&p_conved_h, g_conved_h); cudaGetSymbolAddress((void**)&p_conved_l, g_conved_l);
    cudaGetSymbolAddress((void**)&p_attenc_h, g_attenc_h); cudaGetSymbolAddress((void**)&p_attenc_l, g_attenc_l);
    cudaGetSymbolAddress((void**)&p_comb_h, g_comb_h); cudaGetSymbolAddress((void**)&p_comb_l, g_comb_l);

    const float SC = 0.7071067811865476f;
    const size_t WT_TOTAL = (size_t)LL*2*HH*3*HH;

    // weight prep
    k_transpose_w<<<(unsigned)((WT_TOTAL + 255) / 256), 256>>>(conv_w);
    k_split<<<(HH*EE + 255) / 256, 256>>>(w_eh,  p_weh_h,  p_weh_l,  (size_t)HH*EE);
    k_split<<<(EE*HH + 255) / 256, 256>>>(w_he,  p_whe_h,  p_whe_l,  (size_t)EE*HH);
    k_split<<<(EE*HH + 255) / 256, 256>>>(w_ahe, p_wahe_h, p_wahe_l, (size_t)EE*HH);
    k_split<<<(HH*EE + 255) / 256, 256>>>(w_aeh, p_waeh_h, p_waeh_l, (size_t)HH*EE);
    k_split<<<(unsigned)(((size_t)VV*EE + 255) / 256), 256>>>(w_fc, p_wfc_h, p_wfc_l, (size_t)VV*EE);

    k_zero_pad<<<(BB*2*HH + 255) / 256, 256>>>();
    k_embed<<<(MM*EE + 255) / 256, 256>>>(target, src_emb, pos_emb);

    // conv_input = embedded @ w_eh^T + b_eh  -> padded fp32 buffer, then split
    launch_tc(p_emb_h, p_emb_l, 0, EE, p_weh_h, p_weh_l, b_eh, nullptr, 0, 1.f,
              p_xpad, 1, HH, MM, HH, EE);
    k_split<<<(unsigned)(((size_t)BB*TP*HH + 255) / 256), 256>>>(p_xpad, p_xpad_h, p_xpad_l,
                                                                 (size_t)BB*TP*HH);

    for (int l = 0; l < LL; l++) {
        const size_t wo = (size_t)l*2*HH*3*HH;
        // causal conv as one GEMM: K = 3H contiguous in padded buffer
        launch_tc(p_xpad_h, p_xpad_l, 2, HH, p_wt_h + wo, p_wt_l + wo,
                  conv_b + (size_t)l*2*HH, nullptr, 0, 1.f,
                  p_cbuf, 0, 2*HH, MM, 2*HH, 3*HH);
        k_glu<<<(MM*HH + 255) / 256, 256>>>();
        // comb = (conved @ w_ahe^T + b_ahe + embedded) * sqrt(.5)
        launch_tc(p_conved_h, p_conved_l, 0, HH, p_wahe_h, p_wahe_l,
                  b_ahe, p_emb, EE, SC, p_comb, 0, EE, MM, EE, HH);
        k_energy_softmax<<<MM, 128>>>(encC);
        k_attenc<<<MM, 128>>>(encComb);
        // conved = (att_enc @ w_aeh^T + b_aeh + conved) * sqrt(.5)
        launch_tc(p_attenc_h, p_attenc_l, 0, EE, p_waeh_h, p_waeh_l,
                  b_aeh, p_conved, HH, SC, p_conved, 0, HH, MM, HH, EE);
        // conv_input = (conved + conv_input) * sqrt(.5)  (+ split)
        k_resid<<<(MM*HH + 255) / 256, 256>>>();
    }

    // hidden = conv_input @ w_he^T + b_he, then split
    launch_tc(p_xpad_h, p_xpad_l, 1, HH, p_whe_h, p_whe_l, b_he, nullptr, 0, 1.f,
              p_comb, 0, EE, MM, EE, HH);
    k_split<<<(MM*EE + 255) / 256, 256>>>(p_comb, p_comb_h, p_comb_l, (size_t)MM*EE);
    // logits = hidden @ w_fc^T + b_fc -> d_out
    launch_tc(p_comb_h, p_comb_l, 0, EE, p_wfc_h, p_wfc_l, b_fc, nullptr, 0, 1.f,
              out, 0, VV, MM, VV, EE);

    // attention (last layer) appended after logits
    const long long ATT_OFF = (long long)MM * VV;
    if ((long long)out_size >= ATT_OFF + (long long)MM*SS) {
        k_attcopy<<<(MM*SS + 255) / 256, 256>>>(out + ATT_OFF);
    }
}

// round 8
// speedup vs baseline: 2.1266x; 1.0037x over previous
#include <cuda_runtime.h>
#include <cuda_bf16.h>
#include <math.h>
#include <float.h>
#include <stdint.h>

// Problem dims
#define BB 32
#define TT 100
#define SS 100
#define EE 512
#define HH 1024
#define LL 10
#define VV 32000
#define MM (BB*TT)        // 3200
#define TP (TT+2)         // 102 (left-pad 2)

typedef __nv_bfloat16 bf16;

// ---------------- scratch (static device memory; no allocation) ----------------
__device__ float g_xpad[(size_t)BB*TP*HH];       // conv_input, padded [B][T+2][H]
__device__ float g_emb[(size_t)MM*EE];           // embedded
__device__ float g_conved[(size_t)MM*HH];        // GLU output
__device__ float g_comb[(size_t)MM*EE];          // comb / hidden
__device__ float g_att[(size_t)MM*SS];           // attention
__device__ float g_cbias[(size_t)LL*2*HH];       // interleaved conv bias

// bf16 hi/lo pairs (split precision for tensor-core GEMM)
__device__ bf16 g_wt_h[(size_t)LL*2*HH*3*HH], g_wt_l[(size_t)LL*2*HH*3*HH];
__device__ bf16 g_weh_h[(size_t)HH*EE],  g_weh_l[(size_t)HH*EE];
__device__ bf16 g_whe_h[(size_t)EE*HH],  g_whe_l[(size_t)EE*HH];
__device__ bf16 g_wahe_h[(size_t)EE*HH], g_wahe_l[(size_t)EE*HH];
__device__ bf16 g_waeh_h[(size_t)HH*EE], g_waeh_l[(size_t)HH*EE];
__device__ bf16 g_wfc_h[(size_t)VV*EE],  g_wfc_l[(size_t)VV*EE];
__device__ bf16 g_xpad_h[(size_t)BB*TP*HH], g_xpad_l[(size_t)BB*TP*HH];
__device__ bf16 g_emb_h[(size_t)MM*EE],     g_emb_l[(size_t)MM*EE];
__device__ bf16 g_conved_h[(size_t)MM*HH],  g_conved_l[(size_t)MM*HH];
__device__ bf16 g_attenc_h[(size_t)MM*EE],  g_attenc_l[(size_t)MM*EE];
__device__ bf16 g_comb_h[(size_t)MM*EE],    g_comb_l[(size_t)MM*EE];

__device__ __forceinline__ void splitf(float v, bf16& h, bf16& l) {
    bf16 hh = __float2bfloat16(v);
    h = hh;
    l = __float2bfloat16(v - __bfloat162float(hh));
}

// ---------------- small kernels ----------------

// conv_w [L][2H][H][3] -> wt [L][n'][3][H] (hi/lo), n' INTERLEAVED: 2h<->a_h, 2h+1<->g_h
__global__ void k_transpose_w(const float* __restrict__ w) {
    size_t idx = (size_t)blockIdx.x * 256 + threadIdx.x;
    const size_t total = (size_t)LL*2*HH*3*HH;
    if (idx >= total) return;
    int h = (int)(idx & (HH-1));
    size_t r = idx >> 10;
    int k = (int)(r % 3);
    size_t ln = r / 3;                        // l*2048 + n'
    int np = (int)(ln & (2*HH - 1));
    size_t l = ln >> 11;
    int o = (np & 1) ? (HH + (np >> 1)) : (np >> 1);
    float v = w[(l*2*HH + o)*3*HH + (size_t)h*3 + k];
    splitf(v, g_wt_h[idx], g_wt_l[idx]);
}

// interleave conv bias
__global__ void k_bias_il(const float* __restrict__ cb) {
    int idx = blockIdx.x * 256 + threadIdx.x;     // LL*2048
    if (idx >= LL*2*HH) return;
    int np = idx & (2*HH - 1);
    int l = idx >> 11;
    int o = (np & 1) ? (HH + (np >> 1)) : (np >> 1);
    g_cbias[idx] = cb[l*2*HH + o];
}

// generic fp32 -> hi/lo split (weights only)
__global__ void k_split(const float* __restrict__ src, bf16* __restrict__ h,
                        bf16* __restrict__ l, size_t n) {
    size_t idx = (size_t)blockIdx.x * 256 + threadIdx.x;
    if (idx >= n) return;
    splitf(src[idx], h[idx], l[idx]);
}

__global__ void k_zero_pad() {
    int idx = blockIdx.x * 256 + threadIdx.x;
    if (idx >= BB*2*HH) return;
    int b = idx >> 11;
    int r = (idx >> 10) & 1;
    int h = idx & (HH-1);
    size_t p = (size_t)(b*TP + r)*HH + h;
    g_xpad[p] = 0.f;
    g_xpad_h[p] = __float2bfloat16(0.f);
    g_xpad_l[p] = __float2bfloat16(0.f);
}

__global__ void k_embed(const int* __restrict__ target,
                        const float* __restrict__ src_emb,
                        const float* __restrict__ pos_emb) {
    int idx = blockIdx.x * 256 + threadIdx.x;
    if (idx >= MM*EE) return;
    int m = idx >> 9;
    int e = idx & (EE-1);
    int t = m % TT;
    float v = src_emb[(size_t)target[m]*EE + e] + pos_emb[(size_t)t*EE + e];
    g_emb[idx] = v;
    splitf(v, g_emb_h[idx], g_emb_l[idx]);
}

__global__ void k_attcopy(float* __restrict__ dst) {
    int idx = blockIdx.x * 256 + threadIdx.x;
    if (idx < MM*SS) dst[idx] = g_att[idx];
}

// ---------------- fused attention: energy + softmax + att_enc (+split) ----------------
// grid=100, block=256 (8 warps). Warp owns 4 consecutive m rows (never crosses batch).
__global__ __launch_bounds__(256) void k_att(const float* __restrict__ encC,
                                             const float* __restrict__ encComb) {
    __shared__ float sE[32][104];
    const int w = threadIdx.x >> 5, lane = threadIdx.x & 31;
    const int mw = blockIdx.x * 32 + w * 4;
    const int b = mw / TT;

    // phase 1: energy[r][s] = dot(comb[mw+r], encC[b][s])
    float cr[4][16];
    #pragma unroll
    for (int r = 0; r < 4; r++) {
        const float4* cp = (const float4*)(g_comb + (size_t)(mw + r)*EE + lane*16);
        #pragma unroll
        for (int q = 0; q < 4; q++) {
            float4 v = cp[q];
            cr[r][q*4+0] = v.x; cr[r][q*4+1] = v.y; cr[r][q*4+2] = v.z; cr[r][q*4+3] = v.w;
        }
    }
    const float* ebase = encC + (size_t)b*SS*EE;
    for (int s = 0; s < SS; s++) {
        const float4* ep = (const float4*)(ebase + (size_t)s*EE + lane*16);
        float ev[16];
        #pragma unroll
        for (int q = 0; q < 4; q++) {
            float4 v = ep[q];
            ev[q*4+0] = v.x; ev[q*4+1] = v.y; ev[q*4+2] = v.z; ev[q*4+3] = v.w;
        }
        #pragma unroll
        for (int r = 0; r < 4; r++) {
            float p = 0.f;
            #pragma unroll
            for (int j = 0; j < 16; j++) p += cr[r][j] * ev[j];
            #pragma unroll
            for (int o = 16; o > 0; o >>= 1) p += __shfl_xor_sync(0xffffffffu, p, o);
            if (lane == 0) sE[w*4 + r][s] = p;
        }
    }
    __syncwarp();

    // phase 2: softmax per row
    #pragma unroll
    for (int r = 0; r < 4; r++) {
        float v[4];
        #pragma unroll
        for (int q = 0; q < 4; q++) {
            int s = lane + 32*q;
            v[q] = (s < SS) ? sE[w*4 + r][s] : -FLT_MAX;
        }
        float mx = fmaxf(fmaxf(v[0], v[1]), fmaxf(v[2], v[3]));
        #pragma unroll
        for (int o = 16; o > 0; o >>= 1) mx = fmaxf(mx, __shfl_xor_sync(0xffffffffu, mx, o));
        float e[4]; float sm = 0.f;
        #pragma unroll
        for (int q = 0; q < 4; q++) {
            int s = lane + 32*q;
            e[q] = (s < SS) ? expf(v[q] - mx) : 0.f;
            sm += e[q];
        }
        #pragma unroll
        for (int o = 16; o > 0; o >>= 1) sm += __shfl_xor_sync(0xffffffffu, sm, o);
        float inv = 1.f / sm;
        #pragma unroll
        for (int q = 0; q < 4; q++) {
            int s = lane + 32*q;
            if (s < SS) {
                float a = e[q] * inv;
                sE[w*4 + r][s] = a;
                g_att[(size_t)(mw + r)*SS + s] = a;
            }
        }
    }
    __syncwarp();

    // phase 3: att_enc[r][:] = sum_s att[r][s] * encComb[b][s][:]
    float acc[4][16];
    #pragma unroll
    for (int r = 0; r < 4; r++)
        #pragma unroll
        for (int j = 0; j < 16; j++) acc[r][j] = 0.f;
    const float* cbm = encComb + (size_t)b*SS*EE;
    for (int s = 0; s < SS; s++) {
        const float4* ep = (const float4*)(cbm + (size_t)s*EE + lane*16);
        float ev[16];
        #pragma unroll
        for (int q = 0; q < 4; q++) {
            float4 v = ep[q];
            ev[q*4+0] = v.x; ev[q*4+1] = v.y; ev[q*4+2] = v.z; ev[q*4+3] = v.w;
        }
        #pragma unroll
        for (int r = 0; r < 4; r++) {
            float a = sE[w*4 + r][s];
            #pragma unroll
            for (int j = 0; j < 16; j++) acc[r][j] += a * ev[j];
        }
    }
    #pragma unroll
    for (int r = 0; r < 4; r++) {
        size_t o = (size_t)(mw + r)*EE + lane*16;
        #pragma unroll
        for (int j = 0; j < 16; j++) splitf(acc[r][j], g_attenc_h[o+j], g_attenc_l[o+j]);
    }
}

// ---------------- tensor-core GEMM (bf16x3 split, mma.sync m16n8k16) ----------------
// emode 0: C = scale*(acc + bias + add)            [+ optional split Ch/Cl]
// emode 1: GLU on interleaved column pairs: conved[m][n/2] = a*sigmoid(g)  (+ split)
// emode 2: v = scale*(acc+bias+add); C=v (+split); X[pad] = scale*(v + X[pad]) (+split)
// amode: 0 identity row, 1 padded(+2) row, 2 conv row (padded, no +2, K spans 3 rows)

#define KT 32
#define SSTR 40
#define ARR_SZ (128*SSTR)
#define BUF_SZ (4*ARR_SZ)
#define GSMEM (2*BUF_SZ*2)

__device__ __forceinline__ void ldsm4(uint32_t r[4], unsigned addr) {
    asm volatile("ldmatrix.sync.aligned.m8n8.x4.shared.b16 {%0,%1,%2,%3}, [%4];\n"
        : "=r"(r[0]), "=r"(r[1]), "=r"(r[2]), "=r"(r[3]) : "r"(addr));
}
__device__ __forceinline__ void mma16816(float c[4], const uint32_t a[4],
                                         uint32_t b0, uint32_t b1) {
    asm volatile(
        "mma.sync.aligned.m16n8k16.row.col.f32.bf16.bf16.f32 "
        "{%0,%1,%2,%3},{%4,%5,%6,%7},{%8,%9},{%0,%1,%2,%3};\n"
        : "+f"(c[0]), "+f"(c[1]), "+f"(c[2]), "+f"(c[3])
        : "r"(a[0]), "r"(a[1]), "r"(a[2]), "r"(a[3]), "r"(b0), "r"(b1));
}

__global__ __launch_bounds__(256) void gemm_tc(
    const bf16* __restrict__ Ah, const bf16* __restrict__ Al, int amode, int lda,
    const bf16* __restrict__ Wh, const bf16* __restrict__ Wl,
    const float* __restrict__ bias, const float* __restrict__ add, int ldadd,
    float scale, float* __restrict__ C, bf16* __restrict__ Ch, bf16* __restrict__ Cl,
    int cmode, int ldc, int K, int emode,
    float* __restrict__ X, bf16* __restrict__ Xh, bf16* __restrict__ Xl)
{
    extern __shared__ bf16 sm[];
    const int tid = threadIdx.x;
    const int lane = tid & 31, warp = tid >> 5;
    const int m0 = blockIdx.y * 128, n0 = blockIdx.x * 128;

    size_t aoff[2], woff[2];
    int sdst[2];
    #pragma unroll
    for (int it = 0; it < 2; it++) {
        int seg = tid + it * 256;
        int row = seg >> 2, kq = (seg & 3) * 8;
        int m = m0 + row;
        int rm = m;
        if (amode) { int b = m / TT, t = m - b*TT; rm = b*TP + t + ((amode == 1) ? 2 : 0); }
        aoff[it] = (size_t)rm * lda + kq;
        woff[it] = (size_t)(n0 + row) * K + kq;
        sdst[it] = row * SSTR + kq;
    }

    const unsigned sbase = (unsigned)__cvta_generic_to_shared(sm);
    const int mb = (warp & 3) * 32;
    const int nb = (warp >> 2) * 64;
    const unsigned a_ln = (unsigned)(((lane & 15)*SSTR + (lane >> 4)*8) * 2);
    const unsigned b_ln = (unsigned)((((lane & 7) + ((lane >> 4) << 3))*SSTR
                                     + ((lane >> 3) & 1)*8) * 2);

    float acc[2][8][4];
    #pragma unroll
    for (int i = 0; i < 2; i++)
        #pragma unroll
        for (int j = 0; j < 8; j++)
            #pragma unroll
            for (int q = 0; q < 4; q++) acc[i][j][q] = 0.f;

    uint4 rah[2], ral[2], rbh[2], rbl[2];
    #pragma unroll
    for (int it = 0; it < 2; it++) {
        rah[it] = *(const uint4*)(Ah + aoff[it]);
        ral[it] = *(const uint4*)(Al + aoff[it]);
        rbh[it] = *(const uint4*)(Wh + woff[it]);
        rbl[it] = *(const uint4*)(Wl + woff[it]);
    }
    #pragma unroll
    for (int it = 0; it < 2; it++) {
        *(uint4*)(sm + 0*ARR_SZ + sdst[it]) = rah[it];
        *(uint4*)(sm + 1*ARR_SZ + sdst[it]) = ral[it];
        *(uint4*)(sm + 2*ARR_SZ + sdst[it]) = rbh[it];
        *(uint4*)(sm + 3*ARR_SZ + sdst[it]) = rbl[it];
    }
    __syncthreads();

    const int nK = K / KT;
    for (int s = 0; s < nK; s++) {
        if (s + 1 < nK) {
            int k0 = (s + 1) * KT;
            #pragma unroll
            for (int it = 0; it < 2; it++) {
                rah[it] = *(const uint4*)(Ah + aoff[it] + k0);
                ral[it] = *(const uint4*)(Al + aoff[it] + k0);
                rbh[it] = *(const uint4*)(Wh + woff[it] + k0);
                rbl[it] = *(const uint4*)(Wl + woff[it] + k0);
            }
        }
        unsigned bufb = sbase + (unsigned)((s & 1) * BUF_SZ * 2);
        #pragma unroll
        for (int kk = 0; kk < 2; kk++) {
            unsigned kof = kk * 32;
            uint32_t ah[2][4], al[2][4], bb[4][4];
            unsigned aH = bufb + (0*ARR_SZ)*2 + a_ln + kof;
            unsigned aL = bufb + (1*ARR_SZ)*2 + a_ln + kof;
            unsigned aB = bufb + (2*ARR_SZ)*2 + b_ln + kof;
            ldsm4(ah[0], aH + (unsigned)((mb + 0)  * (SSTR*2)));
            ldsm4(ah[1], aH + (unsigned)((mb + 16) * (SSTR*2)));
            ldsm4(al[0], aL + (unsigned)((mb + 0)  * (SSTR*2)));
            ldsm4(al[1], aL + (unsigned)((mb + 16) * (SSTR*2)));
            #pragma unroll
            for (int tb = 0; tb < 4; tb++)
                ldsm4(bb[tb], aB + (unsigned)((nb + tb*16) * (SSTR*2)));
            #pragma unroll
            for (int tm = 0; tm < 2; tm++)
                #pragma unroll
                for (int j = 0; j < 8; j++)
                    mma16816(acc[tm][j], ah[tm], bb[j>>1][(j&1)*2], bb[j>>1][(j&1)*2+1]);
            #pragma unroll
            for (int tm = 0; tm < 2; tm++)
                #pragma unroll
                for (int j = 0; j < 8; j++)
                    mma16816(acc[tm][j], al[tm], bb[j>>1][(j&1)*2], bb[j>>1][(j&1)*2+1]);
            unsigned aBL = bufb + (3*ARR_SZ)*2 + b_ln + kof;
            #pragma unroll
            for (int tb = 0; tb < 4; tb++)
                ldsm4(bb[tb], aBL + (unsigned)((nb + tb*16) * (SSTR*2)));
            #pragma unroll
            for (int tm = 0; tm < 2; tm++)
                #pragma unroll
                for (int j = 0; j < 8; j++)
                    mma16816(acc[tm][j], ah[tm], bb[j>>1][(j&1)*2], bb[j>>1][(j&1)*2+1]);
        }
        if (s + 1 < nK) {
            bf16* dst = sm + ((s + 1) & 1) * BUF_SZ;
            #pragma unroll
            for (int it = 0; it < 2; it++) {
                *(uint4*)(dst + 0*ARR_SZ + sdst[it]) = rah[it];
                *(uint4*)(dst + 1*ARR_SZ + sdst[it]) = ral[it];
                *(uint4*)(dst + 2*ARR_SZ + sdst[it]) = rbh[it];
                *(uint4*)(dst + 3*ARR_SZ + sdst[it]) = rbl[it];
            }
        }
        __syncthreads();
    }

    // ---------------- epilogue ----------------
    #pragma unroll
    for (int tm = 0; tm < 2; tm++) {
        #pragma unroll
        for (int half = 0; half < 2; half++) {
            int m = m0 + mb + tm*16 + (lane >> 2) + half*8;
            int rm = m;
            if (cmode == 1) { int b = m / TT, t = m - b*TT; rm = b*TP + t + 2; }
            int rmp = 0;
            if (emode == 2) { int b = m / TT, t = m - b*TT; rmp = b*TP + t + 2; }
            size_t crow = (size_t)rm * ldc;
            size_t arow = (size_t)m * ldadd;
            #pragma unroll
            for (int j = 0; j < 8; j++) {
                int n = n0 + nb + j*8 + (lane & 3)*2;
                float v0 = acc[tm][j][half*2 + 0];
                float v1 = acc[tm][j][half*2 + 1];
                if (bias) { v0 += bias[n]; v1 += bias[n+1]; }
                if (emode == 1) {
                    // GLU: v0 = a, v1 = g (interleaved cols); out col = n/2
                    float g = v0 / (1.f + expf(-v1));
                    int h = n >> 1;
                    C[crow + h] = g;
                    splitf(g, Ch[crow + h], Cl[crow + h]);
                } else {
                    if (add) { v0 += add[arow + n]; v1 += add[arow + n + 1]; }
                    v0 *= scale; v1 *= scale;
                    float2 r; r.x = v0; r.y = v1;
                    *(float2*)(C + crow + n) = r;
                    if (Ch) {
                        __nv_bfloat162 hv, lv;
                        splitf(v0, hv.x, lv.x);
                        splitf(v1, hv.y, lv.y);
                        *(__nv_bfloat162*)(Ch + crow + n) = hv;
                        *(__nv_bfloat162*)(Cl + crow + n) = lv;
                    }
                    if (emode == 2) {
                        size_t xrow = (size_t)rmp * ldc;
                        float x0 = (v0 + X[xrow + n]) * scale;
                        float x1 = (v1 + X[xrow + n + 1]) * scale;
                        float2 xr; xr.x = x0; xr.y = x1;
                        *(float2*)(X + xrow + n) = xr;
                        __nv_bfloat162 hv, lv;
                        splitf(x0, hv.x, lv.x);
                        splitf(x1, hv.y, lv.y);
                        *(__nv_bfloat162*)(Xh + xrow + n) = hv;
                        *(__nv_bfloat162*)(Xl + xrow + n) = lv;
                    }
                }
            }
        }
    }
}

static void launch_tc(const bf16* Ah, const bf16* Al, int amode, int lda,
                      const bf16* Wh, const bf16* Wl,
                      const float* bias, const float* add, int ldadd, float scale,
                      float* C, bf16* Ch, bf16* Cl, int cmode, int ldc,
                      int M, int N, int K, int emode = 0,
                      float* X = nullptr, bf16* Xh = nullptr, bf16* Xl = nullptr) {
    dim3 g(N / 128, M / 128);
    gemm_tc<<<g, 256, GSMEM>>>(Ah, Al, amode, lda, Wh, Wl, bias, add, ldadd,
                               scale, C, Ch, Cl, cmode, ldc, K, emode, X, Xh, Xl);
}

// ---------------- launch ----------------
extern "C" void kernel_launch(void* const* d_in, const int* in_sizes, int n_in,
                              void* d_out, int out_size) {
    const int*   target   = (const int*)  d_in[0];
    const float* encC     = (const float*)d_in[1];
    const float* encComb  = (const float*)d_in[2];
    const float* src_emb  = (const float*)d_in[3];
    const float* pos_emb  = (const float*)d_in[4];
    const float* w_eh     = (const float*)d_in[5];
    const float* b_eh     = (const float*)d_in[6];
    const float* w_he     = (const float*)d_in[7];
    const float* b_he     = (const float*)d_in[8];
    const float* w_ahe    = (const float*)d_in[9];
    const float* b_ahe    = (const float*)d_in[10];
    const float* w_aeh    = (const float*)d_in[11];
    const float* b_aeh    = (const float*)d_in[12];
    const float* w_fc     = (const float*)d_in[13];
    const float* b_fc     = (const float*)d_in[14];
    const float* conv_w   = (const float*)d_in[15];
    const float* conv_b   = (const float*)d_in[16];
    float* out = (float*)d_out;

    cudaFuncSetAttribute(gemm_tc, cudaFuncAttributeMaxDynamicSharedMemorySize, GSMEM);

    float *p_xpad, *p_emb, *p_conved, *p_comb, *p_cbias;
    bf16 *p_wt_h, *p_wt_l, *p_weh_h, *p_weh_l, *p_whe_h, *p_whe_l;
    bf16 *p_wahe_h, *p_wahe_l, *p_waeh_h, *p_waeh_l, *p_wfc_h, *p_wfc_l;
    bf16 *p_xpad_h, *p_xpad_l, *p_emb_h, *p_emb_l, *p_conved_h, *p_conved_l;
    bf16 *p_attenc_h, *p_attenc_l, *p_comb_h, *p_comb_l;
    cudaGetSymbolAddress((void**)&p_xpad, g_xpad);
    cudaGetSymbolAddress((void**)&p_emb, g_emb);
    cudaGetSymbolAddress((void**)&p_conved, g_conved);
    cudaGetSymbolAddress((void**)&p_comb, g_comb);
    cudaGetSymbolAddress((void**)&p_cbias, g_cbias);
    cudaGetSymbolAddress((void**)&p_wt_h, g_wt_h);   cudaGetSymbolAddress((void**)&p_wt_l, g_wt_l);
    cudaGetSymbolAddress((void**)&p_weh_h, g_weh_h); cudaGetSymbolAddress((void**)&p_weh_l, g_weh_l);
    cudaGetSymbolAddress((void**)&p_whe_h, g_whe_h); cudaGetSymbolAddress((void**)&p_whe_l, g_whe_l);
    cudaGetSymbolAddress((void**)&p_wahe_h, g_wahe_h); cudaGetSymbolAddress((void**)&p_wahe_l, g_wahe_l);
    cudaGetSymbolAddress((void**)&p_waeh_h, g_waeh_h); cudaGetSymbolAddress((void**)&p_waeh_l, g_waeh_l);
    cudaGetSymbolAddress((void**)&p_wfc_h, g_wfc_h); cudaGetSymbolAddress((void**)&p_wfc_l, g_wfc_l);
    cudaGetSymbolAddress((void**)&p_xpad_h, g_xpad_h); cudaGetSymbolAddress((void**)&p_xpad_l, g_xpad_l);
    cudaGetSymbolAddress((void**)&p_emb_h, g_emb_h); cudaGetSymbolAddress((void**)&p_emb_l, g_emb_l);
    cudaGetSymbolAddress((void**)&p_conved_h, g_conved_h); cudaGetSymbolAddress((void**)&p_conved_l, g_conved_l);
    cudaGetSymbolAddress((void**)&p_attenc_h, g_attenc_h); cudaGetSymbolAddress((void**)&p_attenc_l, g_attenc_l);
    cudaGetSymbolAddress((void**)&p_comb_h, g_comb_h); cudaGetSymbolAddress((void**)&p_comb_l, g_comb_l);

    const float SC = 0.7071067811865476f;
    const size_t WT_TOTAL = (size_t)LL*2*HH*3*HH;

    // weight prep
    k_transpose_w<<<(unsigned)((WT_TOTAL + 255) / 256), 256>>>(conv_w);
    k_bias_il<<<(LL*2*HH + 255) / 256, 256>>>(conv_b);
    k_split<<<(HH*EE + 255) / 256, 256>>>(w_eh,  p_weh_h,  p_weh_l,  (size_t)HH*EE);
    k_split<<<(EE*HH + 255) / 256, 256>>>(w_he,  p_whe_h,  p_whe_l,  (size_t)EE*HH);
    k_split<<<(EE*HH + 255) / 256, 256>>>(w_ahe, p_wahe_h, p_wahe_l, (size_t)EE*HH);
    k_split<<<(HH*EE + 255) / 256, 256>>>(w_aeh, p_waeh_h, p_waeh_l, (size_t)HH*EE);
    k_split<<<(unsigned)(((size_t)VV*EE + 255) / 256), 256>>>(w_fc, p_wfc_h, p_wfc_l, (size_t)VV*EE);

    k_zero_pad<<<(BB*2*HH + 255) / 256, 256>>>();
    k_embed<<<(MM*EE + 255) / 256, 256>>>(target, src_emb, pos_emb);

    // conv_input = embedded @ w_eh^T + b_eh -> padded buffer (fp32 + fused hi/lo)
    launch_tc(p_emb_h, p_emb_l, 0, EE, p_weh_h, p_weh_l, b_eh, nullptr, 0, 1.f,
              p_xpad, p_xpad_h, p_xpad_l, 1, HH, MM, HH, EE);

    for (int l = 0; l < LL; l++) {
        const size_t wo = (size_t)l*2*HH*3*HH;
        // conv (interleaved channels) + fused GLU -> conved fp32 + hi/lo
        launch_tc(p_xpad_h, p_xpad_l, 2, HH, p_wt_h + wo, p_wt_l + wo,
                  p_cbias + (size_t)l*2*HH, nullptr, 0, 1.f,
                  p_conved, p_conved_h, p_conved_l, 0, HH, MM, 2*HH, 3*HH, 1);
        // comb = (conved @ w_ahe^T + b_ahe + embedded) * sqrt(.5)  (fp32 only)
        launch_tc(p_conved_h, p_conved_l, 0, HH, p_wahe_h, p_wahe_l,
                  b_ahe, p_emb, EE, SC, p_comb, nullptr, nullptr, 0, EE, MM, EE, HH);
        // fused energy + softmax + att_enc (+split)
        k_att<<<MM/32, 256>>>(encC, encComb);
        // conved = (att_enc @ w_aeh^T + b_aeh + conved)*SC; xpad = (conved + xpad)*SC
        launch_tc(p_attenc_h, p_attenc_l, 0, EE, p_waeh_h, p_waeh_l,
                  b_aeh, p_conved, HH, SC, p_conved, p_conved_h, p_conved_l,
                  0, HH, MM, HH, EE, 2, p_xpad, p_xpad_h, p_xpad_l);
    }

    // hidden = conv_input @ w_he^T + b_he (fp32 + fused hi/lo)
    launch_tc(p_xpad_h, p_xpad_l, 1, HH, p_whe_h, p_whe_l, b_he, nullptr, 0, 1.f,
              p_comb, p_comb_h, p_comb_l, 0, EE, MM, EE, HH);
    // logits = hidden @ w_fc^T + b_fc -> d_out
    launch_tc(p_comb_h, p_comb_l, 0, EE, p_wfc_h, p_wfc_l, b_fc, nullptr, 0, 1.f,
              out, nullptr, nullptr, 0, VV, MM, VV, EE);

    // attention (last layer) appended after logits
    const long long ATT_OFF = (long long)MM * VV;
    if ((long long)out_size >= ATT_OFF + (long long)MM*SS) {
        k_attcopy<<<(MM*SS + 255) / 256, 256>>>(out + ATT_OFF);
    }
}

// round 9
// speedup vs baseline: 2.2688x; 1.0669x over previous
#include <cuda_runtime.h>
#include <cuda_bf16.h>
#include <math.h>
#include <float.h>
#include <stdint.h>

// Problem dims
#define BB 32
#define TT 100
#define SS 100
#define EE 512
#define HH 1024
#define LL 10
#define VV 32000
#define MM (BB*TT)        // 3200
#define TP (TT+2)         // 102 (left-pad 2)

typedef __nv_bfloat16 bf16;

// ---------------- scratch (static device memory; no allocation) ----------------
__device__ float g_xpad[(size_t)BB*TP*HH];       // conv_input, padded [B][T+2][H]
__device__ float g_emb[(size_t)MM*EE];           // embedded
__device__ float g_conved[(size_t)MM*HH];        // GLU output
__device__ float g_comb[(size_t)MM*EE];          // comb / hidden
__device__ float g_att[(size_t)MM*SS];           // attention
__device__ float g_cbias[(size_t)LL*2*HH];       // interleaved conv bias

// bf16 hi/lo pairs (split precision for tensor-core GEMM)
__device__ bf16 g_wt_h[(size_t)LL*2*HH*3*HH], g_wt_l[(size_t)LL*2*HH*3*HH];
__device__ bf16 g_weh_h[(size_t)HH*EE],  g_weh_l[(size_t)HH*EE];
__device__ bf16 g_whe_h[(size_t)EE*HH],  g_whe_l[(size_t)EE*HH];
__device__ bf16 g_wahe_h[(size_t)EE*HH], g_wahe_l[(size_t)EE*HH];
__device__ bf16 g_waeh_h[(size_t)HH*EE], g_waeh_l[(size_t)HH*EE];
__device__ bf16 g_wfc_h[(size_t)VV*EE],  g_wfc_l[(size_t)VV*EE];
__device__ bf16 g_xpad_h[(size_t)BB*TP*HH], g_xpad_l[(size_t)BB*TP*HH];
__device__ bf16 g_emb_h[(size_t)MM*EE],     g_emb_l[(size_t)MM*EE];
__device__ bf16 g_conved_h[(size_t)MM*HH],  g_conved_l[(size_t)MM*HH];
__device__ bf16 g_attenc_h[(size_t)MM*EE],  g_attenc_l[(size_t)MM*EE];
__device__ bf16 g_comb_h[(size_t)MM*EE],    g_comb_l[(size_t)MM*EE];

__device__ __forceinline__ void splitf(float v, bf16& h, bf16& l) {
    bf16 hh = __float2bfloat16(v);
    h = hh;
    l = __float2bfloat16(v - __bfloat162float(hh));
}

// ---------------- prep kernels (exactly 2 launches before zero/embed) ----------------

// conv_w [L][2H][H][3] -> wt [L][n'][3][H] (hi/lo), n' INTERLEAVED: 2h<->a_h, 2h+1<->g_h
__global__ void k_prep_conv(const float* __restrict__ w) {
    size_t idx = (size_t)blockIdx.x * 256 + threadIdx.x;
    const size_t total = (size_t)LL*2*HH*3*HH;
    if (idx >= total) return;
    int h = (int)(idx & (HH-1));
    size_t r = idx >> 10;
    int k = (int)(r % 3);
    size_t ln = r / 3;                        // l*2048 + n'
    int np = (int)(ln & (2*HH - 1));
    size_t l = ln >> 11;
    int o = (np & 1) ? (HH + (np >> 1)) : (np >> 1);
    float v = w[(l*2*HH + o)*3*HH + (size_t)h*3 + k];
    splitf(v, g_wt_h[idx], g_wt_l[idx]);
}

// everything else: conv-bias interleave + 5 weight splits, fused into one launch
__global__ void k_prep_rest(const float* __restrict__ cb,
                            const float* __restrict__ w_eh, const float* __restrict__ w_he,
                            const float* __restrict__ w_ahe, const float* __restrict__ w_aeh,
                            const float* __restrict__ w_fc) {
    size_t idx = (size_t)blockIdx.x * 256 + threadIdx.x;
    const size_t NB = (size_t)LL*2*HH;        // 20480
    const size_t NW = (size_t)HH*EE;          // 524288
    if (idx < NB) {
        int np = (int)(idx & (2*HH - 1));
        int l = (int)(idx >> 11);
        int o = (np & 1) ? (HH + (np >> 1)) : (np >> 1);
        g_cbias[idx] = cb[(size_t)l*2*HH + o];
        return;
    }
    idx -= NB;
    if (idx < NW) { splitf(w_eh[idx],  g_weh_h[idx],  g_weh_l[idx]);  return; }
    idx -= NW;
    if (idx < NW) { splitf(w_he[idx],  g_whe_h[idx],  g_whe_l[idx]);  return; }
    idx -= NW;
    if (idx < NW) { splitf(w_ahe[idx], g_wahe_h[idx], g_wahe_l[idx]); return; }
    idx -= NW;
    if (idx < NW) { splitf(w_aeh[idx], g_waeh_h[idx], g_waeh_l[idx]); return; }
    idx -= NW;
    if (idx < (size_t)VV*EE) { splitf(w_fc[idx], g_wfc_h[idx], g_wfc_l[idx]); }
}
#define PREP_REST_TOTAL ((size_t)LL*2*HH + 4*(size_t)HH*EE + (size_t)VV*EE)

__global__ void k_zero_pad() {
    int idx = blockIdx.x * 256 + threadIdx.x;
    if (idx >= BB*2*HH) return;
    int b = idx >> 11;
    int r = (idx >> 10) & 1;
    int h = idx & (HH-1);
    size_t p = (size_t)(b*TP + r)*HH + h;
    g_xpad[p] = 0.f;
    g_xpad_h[p] = __float2bfloat16(0.f);
    g_xpad_l[p] = __float2bfloat16(0.f);
}

__global__ void k_embed(const int* __restrict__ target,
                        const float* __restrict__ src_emb,
                        const float* __restrict__ pos_emb) {
    int idx = blockIdx.x * 256 + threadIdx.x;
    if (idx >= MM*EE) return;
    int m = idx >> 9;
    int e = idx & (EE-1);
    int t = m % TT;
    float v = src_emb[(size_t)target[m]*EE + e] + pos_emb[(size_t)t*EE + e];
    g_emb[idx] = v;
    splitf(v, g_emb_h[idx], g_emb_l[idx]);
}

__global__ void k_attcopy(float* __restrict__ dst) {
    int idx = blockIdx.x * 256 + threadIdx.x;
    if (idx < MM*SS) dst[idx] = g_att[idx];
}

// ---------------- fused attention: energy + softmax + att_enc (+split) ----------------
__global__ __launch_bounds__(256) void k_att(const float* __restrict__ encC,
                                             const float* __restrict__ encComb) {
    __shared__ float sE[32][104];
    const int w = threadIdx.x >> 5, lane = threadIdx.x & 31;
    const int mw = blockIdx.x * 32 + w * 4;
    const int b = mw / TT;

    float cr[4][16];
    #pragma unroll
    for (int r = 0; r < 4; r++) {
        const float4* cp = (const float4*)(g_comb + (size_t)(mw + r)*EE + lane*16);
        #pragma unroll
        for (int q = 0; q < 4; q++) {
            float4 v = cp[q];
            cr[r][q*4+0] = v.x; cr[r][q*4+1] = v.y; cr[r][q*4+2] = v.z; cr[r][q*4+3] = v.w;
        }
    }
    const float* ebase = encC + (size_t)b*SS*EE;
    for (int s = 0; s < SS; s++) {
        const float4* ep = (const float4*)(ebase + (size_t)s*EE + lane*16);
        float ev[16];
        #pragma unroll
        for (int q = 0; q < 4; q++) {
            float4 v = ep[q];
            ev[q*4+0] = v.x; ev[q*4+1] = v.y; ev[q*4+2] = v.z; ev[q*4+3] = v.w;
        }
        #pragma unroll
        for (int r = 0; r < 4; r++) {
            float p = 0.f;
            #pragma unroll
            for (int j = 0; j < 16; j++) p += cr[r][j] * ev[j];
            #pragma unroll
            for (int o = 16; o > 0; o >>= 1) p += __shfl_xor_sync(0xffffffffu, p, o);
            if (lane == 0) sE[w*4 + r][s] = p;
        }
    }
    __syncwarp();

    #pragma unroll
    for (int r = 0; r < 4; r++) {
        float v[4];
        #pragma unroll
        for (int q = 0; q < 4; q++) {
            int s = lane + 32*q;
            v[q] = (s < SS) ? sE[w*4 + r][s] : -FLT_MAX;
        }
        float mx = fmaxf(fmaxf(v[0], v[1]), fmaxf(v[2], v[3]));
        #pragma unroll
        for (int o = 16; o > 0; o >>= 1) mx = fmaxf(mx, __shfl_xor_sync(0xffffffffu, mx, o));
        float e[4]; float sm = 0.f;
        #pragma unroll
        for (int q = 0; q < 4; q++) {
            int s = lane + 32*q;
            e[q] = (s < SS) ? expf(v[q] - mx) : 0.f;
            sm += e[q];
        }
        #pragma unroll
        for (int o = 16; o > 0; o >>= 1) sm += __shfl_xor_sync(0xffffffffu, sm, o);
        float inv = 1.f / sm;
        #pragma unroll
        for (int q = 0; q < 4; q++) {
            int s = lane + 32*q;
            if (s < SS) {
                float a = e[q] * inv;
                sE[w*4 + r][s] = a;
                g_att[(size_t)(mw + r)*SS + s] = a;
            }
        }
    }
    __syncwarp();

    float acc[4][16];
    #pragma unroll
    for (int r = 0; r < 4; r++)
        #pragma unroll
        for (int j = 0; j < 16; j++) acc[r][j] = 0.f;
    const float* cbm = encComb + (size_t)b*SS*EE;
    for (int s = 0; s < SS; s++) {
        const float4* ep = (const float4*)(cbm + (size_t)s*EE + lane*16);
        float ev[16];
        #pragma unroll
        for (int q = 0; q < 4; q++) {
            float4 v = ep[q];
            ev[q*4+0] = v.x; ev[q*4+1] = v.y; ev[q*4+2] = v.z; ev[q*4+3] = v.w;
        }
        #pragma unroll
        for (int r = 0; r < 4; r++) {
            float a = sE[w*4 + r][s];
            #pragma unroll
            for (int j = 0; j < 16; j++) acc[r][j] += a * ev[j];
        }
    }
    #pragma unroll
    for (int r = 0; r < 4; r++) {
        size_t o = (size_t)(mw + r)*EE + lane*16;
        #pragma unroll
        for (int j = 0; j < 16; j++) splitf(acc[r][j], g_attenc_h[o+j], g_attenc_l[o+j]);
    }
}

// ---------------- tensor-core GEMM (bf16x3, mma.sync, cp.async 2-stage) ----------------
// emode 0: C = scale*(acc + bias + add)            [+ optional split Ch/Cl]
// emode 1: GLU on interleaved column pairs: conved[m][n/2] = a*sigmoid(g)  (+ split)
// emode 2: v = scale*(acc+bias+add); C=v (+split); X[pad] = scale*(v + X[pad]) (+split)
// amode: 0 identity row, 1 padded(+2) row, 2 conv row (padded, no +2, K spans 3 rows)

#define KT 32
#define SSTR 40
#define ARR_SZ (128*SSTR)
#define BUF_SZ (4*ARR_SZ)
#define GSMEM (2*BUF_SZ*2)          // 81920 bytes

__device__ __forceinline__ void ldsm4(uint32_t r[4], unsigned addr) {
    asm volatile("ldmatrix.sync.aligned.m8n8.x4.shared.b16 {%0,%1,%2,%3}, [%4];\n"
        : "=r"(r[0]), "=r"(r[1]), "=r"(r[2]), "=r"(r[3]) : "r"(addr));
}
__device__ __forceinline__ void mma16816(float c[4], const uint32_t a[4],
                                         uint32_t b0, uint32_t b1) {
    asm volatile(
        "mma.sync.aligned.m16n8k16.row.col.f32.bf16.bf16.f32 "
        "{%0,%1,%2,%3},{%4,%5,%6,%7},{%8,%9},{%0,%1,%2,%3};\n"
        : "+f"(c[0]), "+f"(c[1]), "+f"(c[2]), "+f"(c[3])
        : "r"(a[0]), "r"(a[1]), "r"(a[2]), "r"(a[3]), "r"(b0), "r"(b1));
}
__device__ __forceinline__ void cpasync16(uint32_t dst, const void* src) {
    asm volatile("cp.async.cg.shared.global [%0], [%1], 16;" :: "r"(dst), "l"(src) : "memory");
}
__device__ __forceinline__ void cp_commit() {
    asm volatile("cp.async.commit_group;" ::: "memory");
}
template<int N> __device__ __forceinline__ void cp_wait() {
    asm volatile("cp.async.wait_group %0;" :: "n"(N) : "memory");
}

__global__ __launch_bounds__(256, 2) void gemm_tc(
    const bf16* __restrict__ Ah, const bf16* __restrict__ Al, int amode, int lda,
    const bf16* __restrict__ Wh, const bf16* __restrict__ Wl,
    const float* __restrict__ bias, const float* __restrict__ add, int ldadd,
    float scale, float* __restrict__ C, bf16* __restrict__ Ch, bf16* __restrict__ Cl,
    int cmode, int ldc, int K, int emode,
    float* __restrict__ X, bf16* __restrict__ Xh, bf16* __restrict__ Xl)
{
    extern __shared__ bf16 sm[];
    const int tid = threadIdx.x;
    const int lane = tid & 31, warp = tid >> 5;
    const int m0 = blockIdx.y * 128, n0 = blockIdx.x * 128;

    size_t aoff[2], woff[2];
    uint32_t sdst[2];
    #pragma unroll
    for (int it = 0; it < 2; it++) {
        int seg = tid + it * 256;
        int row = seg >> 2, kq = (seg & 3) * 8;
        int m = m0 + row;
        int rm = m;
        if (amode) { int b = m / TT, t = m - b*TT; rm = b*TP + t + ((amode == 1) ? 2 : 0); }
        aoff[it] = (size_t)rm * lda + kq;
        woff[it] = (size_t)(n0 + row) * K + kq;
        sdst[it] = (uint32_t)(row * SSTR + kq) * 2u;
    }

    const unsigned sbase = (unsigned)__cvta_generic_to_shared(sm);
    const int mb = (warp & 3) * 32;
    const int nb = (warp >> 2) * 64;
    const unsigned a_ln = (unsigned)(((lane & 15)*SSTR + (lane >> 4)*8) * 2);
    const unsigned b_ln = (unsigned)((((lane & 7) + ((lane >> 4) << 3))*SSTR
                                     + ((lane >> 3) & 1)*8) * 2);

    float acc[2][8][4];
    #pragma unroll
    for (int i = 0; i < 2; i++)
        #pragma unroll
        for (int j = 0; j < 8; j++)
            #pragma unroll
            for (int q = 0; q < 4; q++) acc[i][j][q] = 0.f;

    const int nK = K / KT;

    // async stage loader
    #define ISSUE_STAGE(s) do {                                               \
        const size_t k0_ = (size_t)(s) * KT;                                  \
        const unsigned stg_ = sbase + (unsigned)(((s) & 1) * BUF_SZ * 2);     \
        _Pragma("unroll")                                                     \
        for (int it_ = 0; it_ < 2; it_++) {                                   \
            cpasync16(stg_ + 0*ARR_SZ*2 + sdst[it_], Ah + aoff[it_] + k0_);   \
            cpasync16(stg_ + 1*ARR_SZ*2 + sdst[it_], Al + aoff[it_] + k0_);   \
            cpasync16(stg_ + 2*ARR_SZ*2 + sdst[it_], Wh + woff[it_] + k0_);   \
            cpasync16(stg_ + 3*ARR_SZ*2 + sdst[it_], Wl + woff[it_] + k0_);   \
        }                                                                     \
        cp_commit();                                                          \
    } while (0)

    ISSUE_STAGE(0);
    ISSUE_STAGE(1);          // nK >= 16 always here
    cp_wait<1>();
    __syncthreads();

    for (int s = 0; s < nK; s++) {
        unsigned bufb = sbase + (unsigned)((s & 1) * BUF_SZ * 2);
        #pragma unroll
        for (int kk = 0; kk < 2; kk++) {
            unsigned kof = kk * 32;
            uint32_t ah[2][4], al[2][4], bb[4][4];
            unsigned aH = bufb + (0*ARR_SZ)*2 + a_ln + kof;
            unsigned aL = bufb + (1*ARR_SZ)*2 + a_ln + kof;
            unsigned aB = bufb + (2*ARR_SZ)*2 + b_ln + kof;
            ldsm4(ah[0], aH + (unsigned)((mb + 0)  * (SSTR*2)));
            ldsm4(ah[1], aH + (unsigned)((mb + 16) * (SSTR*2)));
            ldsm4(al[0], aL + (unsigned)((mb + 0)  * (SSTR*2)));
            ldsm4(al[1], aL + (unsigned)((mb + 16) * (SSTR*2)));
            #pragma unroll
            for (int tb = 0; tb < 4; tb++)
                ldsm4(bb[tb], aB + (unsigned)((nb + tb*16) * (SSTR*2)));
            #pragma unroll
            for (int tm = 0; tm < 2; tm++)
                #pragma unroll
                for (int j = 0; j < 8; j++)
                    mma16816(acc[tm][j], ah[tm], bb[j>>1][(j&1)*2], bb[j>>1][(j&1)*2+1]);
            #pragma unroll
            for (int tm = 0; tm < 2; tm++)
                #pragma unroll
                for (int j = 0; j < 8; j++)
                    mma16816(acc[tm][j], al[tm], bb[j>>1][(j&1)*2], bb[j>>1][(j&1)*2+1]);
            unsigned aBL = bufb + (3*ARR_SZ)*2 + b_ln + kof;
            #pragma unroll
            for (int tb = 0; tb < 4; tb++)
                ldsm4(bb[tb], aBL + (unsigned)((nb + tb*16) * (SSTR*2)));
            #pragma unroll
            for (int tm = 0; tm < 2; tm++)
                #pragma unroll
                for (int j = 0; j < 8; j++)
                    mma16816(acc[tm][j], ah[tm], bb[j>>1][(j&1)*2], bb[j>>1][(j&1)*2+1]);
        }
        __syncthreads();                      // everyone done reading buf[s&1]
        if (s + 2 < nK) ISSUE_STAGE(s + 2);   // refill into buf[s&1]
        if (s + 1 < nK) {
            if (s + 2 < nK) cp_wait<1>(); else cp_wait<0>();
            __syncthreads();                  // buf[(s+1)&1] visible to all
        }
    }
    #undef ISSUE_STAGE

    // ---------------- epilogue ----------------
    #pragma unroll
    for (int tm = 0; tm < 2; tm++) {
        #pragma unroll
        for (int half = 0; half < 2; half++) {
            int m = m0 + mb + tm*16 + (lane >> 2) + half*8;
            int rm = m;
            if (cmode == 1) { int b = m / TT, t = m - b*TT; rm = b*TP + t + 2; }
            int rmp = 0;
            if (emode == 2) { int b = m / TT, t = m - b*TT; rmp = b*TP + t + 2; }
            size_t crow = (size_t)rm * ldc;
            size_t arow = (size_t)m * ldadd;
            #pragma unroll
            for (int j = 0; j < 8; j++) {
                int n = n0 + nb + j*8 + (lane & 3)*2;
                float v0 = acc[tm][j][half*2 + 0];
                float v1 = acc[tm][j][half*2 + 1];
                if (bias) { v0 += bias[n]; v1 += bias[n+1]; }
                if (emode == 1) {
                    float g = v0 / (1.f + expf(-v1));
                    int h = n >> 1;
                    C[crow + h] = g;
                    splitf(g, Ch[crow + h], Cl[crow + h]);
                } else {
                    if (add) { v0 += add[arow + n]; v1 += add[arow + n + 1]; }
                    v0 *= scale; v1 *= scale;
                    float2 r; r.x = v0; r.y = v1;
                    *(float2*)(C + crow + n) = r;
                    if (Ch) {
                        __nv_bfloat162 hv, lv;
                        splitf(v0, hv.x, lv.x);
                        splitf(v1, hv.y, lv.y);
                        *(__nv_bfloat162*)(Ch + crow + n) = hv;
                        *(__nv_bfloat162*)(Cl + crow + n) = lv;
                    }
                    if (emode == 2) {
                        size_t xrow = (size_t)rmp * ldc;
                        float x0 = (v0 + X[xrow + n]) * scale;
                        float x1 = (v1 + X[xrow + n + 1]) * scale;
                        float2 xr; xr.x = x0; xr.y = x1;
                        *(float2*)(X + xrow + n) = xr;
                        __nv_bfloat162 hv, lv;
                        splitf(x0, hv.x, lv.x);
                        splitf(x1, hv.y, lv.y);
                        *(__nv_bfloat162*)(Xh + xrow + n) = hv;
                        *(__nv_bfloat162*)(Xl + xrow + n) = lv;
                    }
                }
            }
        }
    }
}

static void launch_tc(const bf16* Ah, const bf16* Al, int amode, int lda,
                      const bf16* Wh, const bf16* Wl,
                      const float* bias, const float* add, int ldadd, float scale,
                      float* C, bf16* Ch, bf16* Cl, int cmode, int ldc,
                      int M, int N, int K, int emode = 0,
                      float* X = nullptr, bf16* Xh = nullptr, bf16* Xl = nullptr) {
    dim3 g(N / 128, M / 128);
    gemm_tc<<<g, 256, GSMEM>>>(Ah, Al, amode, lda, Wh, Wl, bias, add, ldadd,
                               scale, C, Ch, Cl, cmode, ldc, K, emode, X, Xh, Xl);
}

// ---------------- launch ----------------
extern "C" void kernel_launch(void* const* d_in, const int* in_sizes, int n_in,
                              void* d_out, int out_size) {
    const int*   target   = (const int*)  d_in[0];
    const float* encC     = (const float*)d_in[1];
    const float* encComb  = (const float*)d_in[2];
    const float* src_emb  = (const float*)d_in[3];
    const float* pos_emb  = (const float*)d_in[4];
    const float* w_eh     = (const float*)d_in[5];
    const float* b_eh     = (const float*)d_in[6];
    const float* w_he     = (const float*)d_in[7];
    const float* b_he     = (const float*)d_in[8];
    const float* w_ahe    = (const float*)d_in[9];
    const float* b_ahe    = (const float*)d_in[10];
    const float* w_aeh    = (const float*)d_in[11];
    const float* b_aeh    = (const float*)d_in[12];
    const float* w_fc     = (const float*)d_in[13];
    const float* b_fc     = (const float*)d_in[14];
    const float* conv_w   = (const float*)d_in[15];
    const float* conv_b   = (const float*)d_in[16];
    float* out = (float*)d_out;

    cudaFuncSetAttribute(gemm_tc, cudaFuncAttributeMaxDynamicSharedMemorySize, GSMEM);

    float *p_xpad, *p_emb, *p_conved, *p_comb, *p_cbias;
    bf16 *p_wt_h, *p_wt_l, *p_weh_h, *p_weh_l, *p_whe_h, *p_whe_l;
    bf16 *p_wahe_h, *p_wahe_l, *p_waeh_h, *p_waeh_l, *p_wfc_h, *p_wfc_l;
    bf16 *p_xpad_h, *p_xpad_l, *p_emb_h, *p_emb_l, *p_conved_h, *p_conved_l;
    bf16 *p_attenc_h, *p_attenc_l, *p_comb_h, *p_comb_l;
    cudaGetSymbolAddress((void**)&p_xpad, g_xpad);
    cudaGetSymbolAddress((void**)&p_emb, g_emb);
    cudaGetSymbolAddress((void**)&p_conved, g_conved);
    cudaGetSymbolAddress((void**)&p_comb, g_comb);
    cudaGetSymbolAddress((void**)&p_cbias, g_cbias);
    cudaGetSymbolAddress((void**)&p_wt_h, g_wt_h);   cudaGetSymbolAddress((void**)&p_wt_l, g_wt_l);
    cudaGetSymbolAddress((void**)&p_weh_h, g_weh_h); cudaGetSymbolAddress((void**)&p_weh_l, g_weh_l);
    cudaGetSymbolAddress((void**)&p_whe_h, g_whe_h); cudaGetSymbolAddress((void**)&p_whe_l, g_whe_l);
    cudaGetSymbolAddress((void**)&p_wahe_h, g_wahe_h); cudaGetSymbolAddress((void**)&p_wahe_l, g_wahe_l);
    cudaGetSymbolAddress((void**)&p_waeh_h, g_waeh_h); cudaGetSymbolAddress((void**)&p_waeh_l, g_waeh_l);
    cudaGetSymbolAddress((void**)&p_wfc_h, g_wfc_h); cudaGetSymbolAddress((void**)&p_wfc_l, g_wfc_l);
    cudaGetSymbolAddress((void**)&p_xpad_h, g_xpad_h); cudaGetSymbolAddress((void**)&p_xpad_l, g_xpad_l);
    cudaGetSymbolAddress((void**)&p_emb_h, g_emb_h); cudaGetSymbolAddress((void**)&p_emb_l, g_emb_l);
    cudaGetSymbolAddress((void**)&p_conved_h, g_conved_h); cudaGetSymbolAddress((void**)&p_conved_l, g_conved_l);
    cudaGetSymbolAddress((void**)&p_attenc_h, g_attenc_h); cudaGetSymbolAddress((void**)&p_attenc_l, g_attenc_l);
    cudaGetSymbolAddress((void**)&p_comb_h, g_comb_h); cudaGetSymbolAddress((void**)&p_comb_l, g_comb_l);

    const float SC = 0.7071067811865476f;
    const size_t WT_TOTAL = (size_t)LL*2*HH*3*HH;

    // launch 1: conv weight transpose+split
    k_prep_conv<<<(unsigned)((WT_TOTAL + 255) / 256), 256>>>(conv_w);
    // launch 2: all other weight prep
    k_prep_rest<<<(unsigned)((PREP_REST_TOTAL + 255) / 256), 256>>>(
        conv_b, w_eh, w_he, w_ahe, w_aeh, w_fc);
    // launch 3
    k_zero_pad<<<(BB*2*HH + 255) / 256, 256>>>();
    // launch 4
    k_embed<<<(MM*EE + 255) / 256, 256>>>(target, src_emb, pos_emb);

    // launch 5: conv_input = embedded @ w_eh^T + b_eh (fp32 + fused hi/lo)
    launch_tc(p_emb_h, p_emb_l, 0, EE, p_weh_h, p_weh_l, b_eh, nullptr, 0, 1.f,
              p_xpad, p_xpad_h, p_xpad_l, 1, HH, MM, HH, EE);

    for (int l = 0; l < LL; l++) {
        const size_t wo = (size_t)l*2*HH*3*HH;
        // launch 6 (l=0, profiled by ncu -s 5 -c 1): conv + fused GLU
        launch_tc(p_xpad_h, p_xpad_l, 2, HH, p_wt_h + wo, p_wt_l + wo,
                  p_cbias + (size_t)l*2*HH, nullptr, 0, 1.f,
                  p_conved, p_conved_h, p_conved_l, 0, HH, MM, 2*HH, 3*HH, 1);
        // comb = (conved @ w_ahe^T + b_ahe + embedded) * sqrt(.5)
        launch_tc(p_conved_h, p_conved_l, 0, HH, p_wahe_h, p_wahe_l,
                  b_ahe, p_emb, EE, SC, p_comb, nullptr, nullptr, 0, EE, MM, EE, HH);
        // fused energy + softmax + att_enc (+split)
        k_att<<<MM/32, 256>>>(encC, encComb);
        // conved = (att_enc @ w_aeh^T + b_aeh + conved)*SC; xpad = (conved + xpad)*SC
        launch_tc(p_attenc_h, p_attenc_l, 0, EE, p_waeh_h, p_waeh_l,
                  b_aeh, p_conved, HH, SC, p_conved, p_conved_h, p_conved_l,
                  0, HH, MM, HH, EE, 2, p_xpad, p_xpad_h, p_xpad_l);
    }

    // hidden = conv_input @ w_he^T + b_he (fp32 + fused hi/lo)
    launch_tc(p_xpad_h, p_xpad_l, 1, HH, p_whe_h, p_whe_l, b_he, nullptr, 0, 1.f,
              p_comb, p_comb_h, p_comb_l, 0, EE, MM, EE, HH);
    // logits = hidden @ w_fc^T + b_fc -> d_out
    launch_tc(p_comb_h, p_comb_l, 0, EE, p_wfc_h, p_wfc_l, b_fc, nullptr, 0, 1.f,
              out, nullptr, nullptr, 0, VV, MM, VV, EE);

    // attention (last layer) appended after logits
    const long long ATT_OFF = (long long)MM * VV;
    if ((long long)out_size >= ATT_OFF + (long long)MM*SS) {
        k_attcopy<<<(MM*SS + 255) / 256, 256>>>(out + ATT_OFF);
    }
}

// round 11
// speedup vs baseline: 2.4185x; 1.0660x over previous
#include <cuda_runtime.h>
#include <cuda_bf16.h>
#include <math.h>
#include <float.h>
#include <stdint.h>

// Problem dims
#define BB 32
#define TT 100
#define SS 100
#define EE 512
#define HH 1024
#define LL 10
#define VV 32000
#define MM (BB*TT)        // 3200
#define TP (TT+2)         // 102 (left-pad 2)

typedef __nv_bfloat16 bf16;

// ---------------- scratch (static device memory; no allocation) ----------------
__device__ float g_xpad[(size_t)BB*TP*HH];
__device__ float g_emb[(size_t)MM*EE];
__device__ float g_conved[(size_t)MM*HH];
__device__ float g_comb[(size_t)MM*EE];
__device__ float g_att[(size_t)MM*SS];
__device__ float g_cbias[(size_t)LL*2*HH];

__device__ bf16 g_wt_h[(size_t)LL*2*HH*3*HH], g_wt_l[(size_t)LL*2*HH*3*HH];
__device__ bf16 g_weh_h[(size_t)HH*EE],  g_weh_l[(size_t)HH*EE];
__device__ bf16 g_whe_h[(size_t)EE*HH],  g_whe_l[(size_t)EE*HH];
__device__ bf16 g_wahe_h[(size_t)EE*HH], g_wahe_l[(size_t)EE*HH];
__device__ bf16 g_waeh_h[(size_t)HH*EE], g_waeh_l[(size_t)HH*EE];
__device__ bf16 g_wfc_h[(size_t)VV*EE],  g_wfc_l[(size_t)VV*EE];
__device__ bf16 g_xpad_h[(size_t)BB*TP*HH], g_xpad_l[(size_t)BB*TP*HH];
__device__ bf16 g_emb_h[(size_t)MM*EE],     g_emb_l[(size_t)MM*EE];
__device__ bf16 g_conved_h[(size_t)MM*HH],  g_conved_l[(size_t)MM*HH];
__device__ bf16 g_attenc_h[(size_t)MM*EE],  g_attenc_l[(size_t)MM*EE];
__device__ bf16 g_comb_h[(size_t)MM*EE],    g_comb_l[(size_t)MM*EE];

__device__ __forceinline__ void splitf(float v, bf16& h, bf16& l) {
    bf16 hh = __float2bfloat16(v);
    h = hh;
    l = __float2bfloat16(v - __bfloat162float(hh));
}

// ---------------- prep: ONE kernel for all weight prep ----------------
#define WT_TOTAL ((size_t)LL*2*HH*3*HH)                     // 62,914,560
#define PREP_REST_TOTAL ((size_t)LL*2*HH + 4*(size_t)HH*EE + (size_t)VV*EE)
#define PREP_TOTAL (WT_TOTAL + PREP_REST_TOTAL)

__global__ void k_prep(const float* __restrict__ w, const float* __restrict__ cb,
                       const float* __restrict__ w_eh, const float* __restrict__ w_he,
                       const float* __restrict__ w_ahe, const float* __restrict__ w_aeh,
                       const float* __restrict__ w_fc) {
    size_t idx = (size_t)blockIdx.x * 256 + threadIdx.x;
    if (idx < WT_TOTAL) {
        // conv_w [L][2H][H][3] -> wt [L][n'][3][H], n' interleaved (2h = a_h, 2h+1 = g_h)
        int h = (int)(idx & (HH-1));
        size_t r = idx >> 10;
        int k = (int)(r % 3);
        size_t ln = r / 3;
        int np = (int)(ln & (2*HH - 1));
        size_t l = ln >> 11;
        int o = (np & 1) ? (HH + (np >> 1)) : (np >> 1);
        float v = w[(l*2*HH + o)*3*HH + (size_t)h*3 + k];
        splitf(v, g_wt_h[idx], g_wt_l[idx]);
        return;
    }
    idx -= WT_TOTAL;
    const size_t NB = (size_t)LL*2*HH;
    const size_t NW = (size_t)HH*EE;
    if (idx < NB) {
        int np = (int)(idx & (2*HH - 1));
        int l = (int)(idx >> 11);
        int o = (np & 1) ? (HH + (np >> 1)) : (np >> 1);
        g_cbias[idx] = cb[(size_t)l*2*HH + o];
        return;
    }
    idx -= NB;
    if (idx < NW) { splitf(w_eh[idx],  g_weh_h[idx],  g_weh_l[idx]);  return; }
    idx -= NW;
    if (idx < NW) { splitf(w_he[idx],  g_whe_h[idx],  g_whe_l[idx]);  return; }
    idx -= NW;
    if (idx < NW) { splitf(w_ahe[idx], g_wahe_h[idx], g_wahe_l[idx]); return; }
    idx -= NW;
    if (idx < NW) { splitf(w_aeh[idx], g_waeh_h[idx], g_waeh_l[idx]); return; }
    idx -= NW;
    if (idx < (size_t)VV*EE) { splitf(w_fc[idx], g_wfc_h[idx], g_wfc_l[idx]); }
}

// embed + zero pad rows, one launch
__global__ void k_embed(const int* __restrict__ target,
                        const float* __restrict__ src_emb,
                        const float* __restrict__ pos_emb) {
    int idx = blockIdx.x * 256 + threadIdx.x;
    if (idx < MM*EE) {
        int m = idx >> 9;
        int e = idx & (EE-1);
        int t = m % TT;
        float v = src_emb[(size_t)target[m]*EE + e] + pos_emb[(size_t)t*EE + e];
        g_emb[idx] = v;
        splitf(v, g_emb_h[idx], g_emb_l[idx]);
        return;
    }
    int j = idx - MM*EE;
    if (j < BB*2*HH) {
        int b = j >> 11;
        int r = (j >> 10) & 1;
        int h = j & (HH-1);
        size_t p = (size_t)(b*TP + r)*HH + h;
        g_xpad[p] = 0.f;
        g_xpad_h[p] = __float2bfloat16(0.f);
        g_xpad_l[p] = __float2bfloat16(0.f);
    }
}

__global__ void k_attcopy(float* __restrict__ dst) {
    int idx = blockIdx.x * 256 + threadIdx.x;
    if (idx < MM*SS) dst[idx] = g_att[idx];
}

// ---------------- fused attention: energy + softmax + att_enc (+split) ----------------
__global__ __launch_bounds__(256) void k_att(const float* __restrict__ encC,
                                             const float* __restrict__ encComb) {
    __shared__ float sE[32][104];
    const int w = threadIdx.x >> 5, lane = threadIdx.x & 31;
    const int mw = blockIdx.x * 32 + w * 4;
    const int b = mw / TT;

    float cr[4][16];
    #pragma unroll
    for (int r = 0; r < 4; r++) {
        const float4* cp = (const float4*)(g_comb + (size_t)(mw + r)*EE + lane*16);
        #pragma unroll
        for (int q = 0; q < 4; q++) {
            float4 v = cp[q];
            cr[r][q*4+0] = v.x; cr[r][q*4+1] = v.y; cr[r][q*4+2] = v.z; cr[r][q*4+3] = v.w;
        }
    }
    const float* ebase = encC + (size_t)b*SS*EE;
    for (int s = 0; s < SS; s++) {
        const float4* ep = (const float4*)(ebase + (size_t)s*EE + lane*16);
        float ev[16];
        #pragma unroll
        for (int q = 0; q < 4; q++) {
            float4 v = ep[q];
            ev[q*4+0] = v.x; ev[q*4+1] = v.y; ev[q*4+2] = v.z; ev[q*4+3] = v.w;
        }
        #pragma unroll
        for (int r = 0; r < 4; r++) {
            float p = 0.f;
            #pragma unroll
            for (int j = 0; j < 16; j++) p += cr[r][j] * ev[j];
            #pragma unroll
            for (int o = 16; o > 0; o >>= 1) p += __shfl_xor_sync(0xffffffffu, p, o);
            if (lane == 0) sE[w*4 + r][s] = p;
        }
    }
    __syncwarp();

    #pragma unroll
    for (int r = 0; r < 4; r++) {
        float v[4];
        #pragma unroll
        for (int q = 0; q < 4; q++) {
            int s = lane + 32*q;
            v[q] = (s < SS) ? sE[w*4 + r][s] : -FLT_MAX;
        }
        float mx = fmaxf(fmaxf(v[0], v[1]), fmaxf(v[2], v[3]));
        #pragma unroll
        for (int o = 16; o > 0; o >>= 1) mx = fmaxf(mx, __shfl_xor_sync(0xffffffffu, mx, o));
        float e[4]; float sm = 0.f;
        #pragma unroll
        for (int q = 0; q < 4; q++) {
            int s = lane + 32*q;
            e[q] = (s < SS) ? expf(v[q] - mx) : 0.f;
            sm += e[q];
        }
        #pragma unroll
        for (int o = 16; o > 0; o >>= 1) sm += __shfl_xor_sync(0xffffffffu, sm, o);
        float inv = 1.f / sm;
        #pragma unroll
        for (int q = 0; q < 4; q++) {
            int s = lane + 32*q;
            if (s < SS) {
                float a = e[q] * inv;
                sE[w*4 + r][s] = a;
                g_att[(size_t)(mw + r)*SS + s] = a;
            }
        }
    }
    __syncwarp();

    float acc[4][16];
    #pragma unroll
    for (int r = 0; r < 4; r++)
        #pragma unroll
        for (int j = 0; j < 16; j++) acc[r][j] = 0.f;
    const float* cbm = encComb + (size_t)b*SS*EE;
    for (int s = 0; s < SS; s++) {
        const float4* ep = (const float4*)(cbm + (size_t)s*EE + lane*16);
        float ev[16];
        #pragma unroll
        for (int q = 0; q < 4; q++) {
            float4 v = ep[q];
            ev[q*4+0] = v.x; ev[q*4+1] = v.y; ev[q*4+2] = v.z; ev[q*4+3] = v.w;
        }
        #pragma unroll
        for (int r = 0; r < 4; r++) {
            float a = sE[w*4 + r][s];
            #pragma unroll
            for (int j = 0; j < 16; j++) acc[r][j] += a * ev[j];
        }
    }
    #pragma unroll
    for (int r = 0; r < 4; r++) {
        size_t o = (size_t)(mw + r)*EE + lane*16;
        #pragma unroll
        for (int j = 0; j < 16; j++) splitf(acc[r][j], g_attenc_h[o+j], g_attenc_l[o+j]);
    }
}

// ---------------- tensor-core GEMM (bf16x3, 64x128 tile, SW64, 3-stage cp.async) ----------------
// emode 0: C = scale*(acc + bias + add)            [+ optional split Ch/Cl]
// emode 1: GLU on interleaved column pairs: conved[m][n/2] = a*sigmoid(g)  (+ split)
// emode 2: v = scale*(acc+bias+add); C=v (+split); X[pad] = scale*(v + X[pad]) (+split)
// amode: 0 identity row, 1 padded(+2) row, 2 conv row (padded, no +2, K spans 3 rows)

#define TMQ 64
#define TNQ 128
#define KT 32
#define A_H_OFF 0
#define A_L_OFF 4096
#define B_H_OFF 8192
#define B_L_OFF 16384
#define STAGE 24576
#define NSTG 3
#define DYN_BYTES (NSTG*STAGE + 128)

__device__ __forceinline__ uint32_t swz64(uint32_t x) { return x ^ ((x >> 3) & 0x30); }

__device__ __forceinline__ void ldsm4(uint32_t r[4], unsigned addr) {
    asm volatile("ldmatrix.sync.aligned.m8n8.x4.shared.b16 {%0,%1,%2,%3}, [%4];\n"
        : "=r"(r[0]), "=r"(r[1]), "=r"(r[2]), "=r"(r[3]) : "r"(addr));
}
__device__ __forceinline__ void mma16816(float c[4], const uint32_t a[4],
                                         uint32_t b0, uint32_t b1) {
    asm volatile(
        "mma.sync.aligned.m16n8k16.row.col.f32.bf16.bf16.f32 "
        "{%0,%1,%2,%3},{%4,%5,%6,%7},{%8,%9},{%0,%1,%2,%3};\n"
        : "+f"(c[0]), "+f"(c[1]), "+f"(c[2]), "+f"(c[3])
        : "r"(a[0]), "r"(a[1]), "r"(a[2]), "r"(a[3]), "r"(b0), "r"(b1));
}
__device__ __forceinline__ void cpasync16(uint32_t dst, const void* src) {
    asm volatile("cp.async.cg.shared.global [%0], [%1], 16;" :: "r"(dst), "l"(src) : "memory");
}
__device__ __forceinline__ void cp_commit() {
    asm volatile("cp.async.commit_group;" ::: "memory");
}
template<int N> __device__ __forceinline__ void cp_wait() {
    asm volatile("cp.async.wait_group %0;" :: "n"(N) : "memory");
}

__global__ __launch_bounds__(256, 3) void gemm_tc(
    const bf16* __restrict__ Ah, const bf16* __restrict__ Al, int amode, int lda,
    const bf16* __restrict__ Wh, const bf16* __restrict__ Wl,
    const float* __restrict__ bias, const float* __restrict__ add, int ldadd,
    float scale, float* __restrict__ C, bf16* __restrict__ Ch, bf16* __restrict__ Cl,
    int cmode, int ldc, int K, int emode,
    float* __restrict__ X, bf16* __restrict__ Xh, bf16* __restrict__ Xl)
{
    extern __shared__ char dynsm[];
    const int tid = threadIdx.x;
    const int lane = tid & 31, warp = tid >> 5;
    const int m0 = blockIdx.y * TMQ, n0 = blockIdx.x * TNQ;
    const unsigned sbase = ((unsigned)__cvta_generic_to_shared(dynsm) + 127u) & ~127u;

    // ---- load maps ----
    // A: 64 rows x 4 chunks(16B) = 256 -> one per thread
    size_t a_go; uint32_t a_sd;
    {
        int row = tid >> 2, c = tid & 3;
        int m = m0 + row, rm = m;
        if (amode) { int b = m / TT, t = m - b*TT; rm = b*TP + t + ((amode == 1) ? 2 : 0); }
        a_go = (size_t)rm * lda + c * 8;
        a_sd = swz64((uint32_t)(row * 64 + c * 16));
    }
    // B: 128 rows x 4 chunks = 512 -> two per thread
    size_t w_go[2]; uint32_t b_sd[2];
    #pragma unroll
    for (int i = 0; i < 2; i++) {
        int idx = tid + i * 256;
        int row = idx >> 2, c = idx & 3;
        w_go[i] = (size_t)(n0 + row) * K + c * 8;
        b_sd[i] = swz64((uint32_t)(row * 64 + c * 16));
    }

    const int wm = warp & 1;           // 2 warps in M
    const int wn = warp >> 1;          // 4 warps in N

    float acc[2][4][4];
    #pragma unroll
    for (int i = 0; i < 2; i++)
        #pragma unroll
        for (int j = 0; j < 4; j++)
            #pragma unroll
            for (int q = 0; q < 4; q++) acc[i][j][q] = 0.f;

    const int nK = K / KT;

    #define ISSUE_STAGE(s) do {                                               \
        const size_t k0_ = (size_t)(s) * KT;                                  \
        const unsigned stg_ = sbase + (unsigned)(((s) % NSTG) * STAGE);       \
        cpasync16(stg_ + A_H_OFF + a_sd, Ah + a_go + k0_);                    \
        cpasync16(stg_ + A_L_OFF + a_sd, Al + a_go + k0_);                    \
        _Pragma("unroll")                                                     \
        for (int i_ = 0; i_ < 2; i_++) {                                      \
            cpasync16(stg_ + B_H_OFF + b_sd[i_], Wh + w_go[i_] + k0_);        \
            cpasync16(stg_ + B_L_OFF + b_sd[i_], Wl + w_go[i_] + k0_);        \
        }                                                                     \
        cp_commit();                                                          \
    } while (0)

    ISSUE_STAGE(0); ISSUE_STAGE(1); ISSUE_STAGE(2);   // nK >= 16 always
    cp_wait<2>();
    __syncthreads();

    for (int s = 0; s < nK; s++) {
        const unsigned bufb = sbase + (unsigned)((s % NSTG) * STAGE);
        #pragma unroll
        for (int kk = 0; kk < 2; kk++) {
            uint32_t ah[2][4], al[2][4], bb[2][4];
            #pragma unroll
            for (int tm = 0; tm < 2; tm++) {
                uint32_t lin = (uint32_t)((wm*32 + tm*16 + (lane & 15)) * 64
                                          + kk*32 + (lane >> 4) * 16);
                ldsm4(ah[tm], bufb + A_H_OFF + swz64(lin));
                ldsm4(al[tm], bufb + A_L_OFF + swz64(lin));
            }
            #pragma unroll
            for (int tb = 0; tb < 2; tb++) {
                uint32_t lin = (uint32_t)((wn*32 + tb*16 + (lane & 7) + ((lane >> 4) << 3)) * 64
                                          + kk*32 + (((lane >> 3) & 1) << 4));
                ldsm4(bb[tb], bufb + B_H_OFF + swz64(lin));
            }
            // hi*hi
            #pragma unroll
            for (int tm = 0; tm < 2; tm++)
                #pragma unroll
                for (int j = 0; j < 4; j++)
                    mma16816(acc[tm][j], ah[tm], bb[j>>1][(j&1)*2], bb[j>>1][(j&1)*2+1]);
            // lo*hi
            #pragma unroll
            for (int tm = 0; tm < 2; tm++)
                #pragma unroll
                for (int j = 0; j < 4; j++)
                    mma16816(acc[tm][j], al[tm], bb[j>>1][(j&1)*2], bb[j>>1][(j&1)*2+1]);
            // reload B_lo over bb
            #pragma unroll
            for (int tb = 0; tb < 2; tb++) {
                uint32_t lin = (uint32_t)((wn*32 + tb*16 + (lane & 7) + ((lane >> 4) << 3)) * 64
                                          + kk*32 + (((lane >> 3) & 1) << 4));
                ldsm4(bb[tb], bufb + B_L_OFF + swz64(lin));
            }
            // hi*lo
            #pragma unroll
            for (int tm = 0; tm < 2; tm++)
                #pragma unroll
                for (int j = 0; j < 4; j++)
                    mma16816(acc[tm][j], ah[tm], bb[j>>1][(j&1)*2], bb[j>>1][(j&1)*2+1]);
        }
        __syncthreads();                       // all warps done with buf[s%NSTG]
        if (s + 1 < nK) {
            if (s + 3 < nK) { ISSUE_STAGE(s + 3); cp_wait<2>(); }
            else if (s + 2 < nK) cp_wait<1>();
            else cp_wait<0>();
            __syncthreads();
        }
    }
    #undef ISSUE_STAGE

    // ---------------- epilogue ----------------
    #pragma unroll
    for (int tm = 0; tm < 2; tm++) {
        #pragma unroll
        for (int half = 0; half < 2; half++) {
            int m = m0 + wm*32 + tm*16 + (lane >> 2) + half*8;
            int rm = m;
            if (cmode == 1) { int b = m / TT, t = m - b*TT; rm = b*TP + t + 2; }
            int rmp = 0;
            if (emode == 2) { int b = m / TT, t = m - b*TT; rmp = b*TP + t + 2; }
            size_t crow = (size_t)rm * ldc;
            size_t arow = (size_t)m * ldadd;
            #pragma unroll
            for (int j = 0; j < 4; j++) {
                int n = n0 + wn*32 + j*8 + (lane & 3)*2;
                float v0 = acc[tm][j][half*2 + 0];
                float v1 = acc[tm][j][half*2 + 1];
                if (bias) { v0 += bias[n]; v1 += bias[n+1]; }
                if (emode == 1) {
                    float g = v0 / (1.f + expf(-v1));
                    int h = n >> 1;
                    C[crow + h] = g;
                    splitf(g, Ch[crow + h], Cl[crow + h]);
                } else {
                    if (add) { v0 += add[arow + n]; v1 += add[arow + n + 1]; }
                    v0 *= scale; v1 *= scale;
                    float2 r; r.x = v0; r.y = v1;
                    *(float2*)(C + crow + n) = r;
                    if (Ch) {
                        __nv_bfloat162 hv, lv;
                        splitf(v0, hv.x, lv.x);
                        splitf(v1, hv.y, lv.y);
                        *(__nv_bfloat162*)(Ch + crow + n) = hv;
                        *(__nv_bfloat162*)(Cl + crow + n) = lv;
                    }
                    if (emode == 2) {
                        size_t xrow = (size_t)rmp * ldc;
                        float x0 = (v0 + X[xrow + n]) * scale;
                        float x1 = (v1 + X[xrow + n + 1]) * scale;
                        float2 xr; xr.x = x0; xr.y = x1;
                        *(float2*)(X + xrow + n) = xr;
                        __nv_bfloat162 hv, lv;
                        splitf(x0, hv.x, lv.x);
                        splitf(x1, hv.y, lv.y);
                        *(__nv_bfloat162*)(Xh + xrow + n) = hv;
                        *(__nv_bfloat162*)(Xl + xrow + n) = lv;
                    }
                }
            }
        }
    }
}

static void launch_tc(const bf16* Ah, const bf16* Al, int amode, int lda,
                      const bf16* Wh, const bf16* Wl,
                      const float* bias, const float* add, int ldadd, float scale,
                      float* C, bf16* Ch, bf16* Cl, int cmode, int ldc,
                      int M, int N, int K, int emode = 0,
                      float* X = nullptr, bf16* Xh = nullptr, bf16* Xl = nullptr) {
    dim3 g(N / TNQ, M / TMQ);
    gemm_tc<<<g, 256, DYN_BYTES>>>(Ah, Al, amode, lda, Wh, Wl, bias, add, ldadd,
                                   scale, C, Ch, Cl, cmode, ldc, K, emode, X, Xh, Xl);
}

// ---------------- launch ----------------
extern "C" void kernel_launch(void* const* d_in, const int* in_sizes, int n_in,
                              void* d_out, int out_size) {
    const int*   target   = (const int*)  d_in[0];
    const float* encC     = (const float*)d_in[1];
    const float* encComb  = (const float*)d_in[2];
    const float* src_emb  = (const float*)d_in[3];
    const float* pos_emb  = (const float*)d_in[4];
    const float* w_eh     = (const float*)d_in[5];
    const float* b_eh     = (const float*)d_in[6];
    const float* w_he     = (const float*)d_in[7];
    const float* b_he     = (const float*)d_in[8];
    const float* w_ahe    = (const float*)d_in[9];
    const float* b_ahe    = (const float*)d_in[10];
    const float* w_aeh    = (const float*)d_in[11];
    const float* b_aeh    = (const float*)d_in[12];
    const float* w_fc     = (const float*)d_in[13];
    const float* b_fc     = (const float*)d_in[14];
    const float* conv_w   = (const float*)d_in[15];
    const float* conv_b   = (const float*)d_in[16];
    float* out = (float*)d_out;

    cudaFuncSetAttribute(gemm_tc, cudaFuncAttributeMaxDynamicSharedMemorySize, DYN_BYTES);

    float *p_xpad, *p_emb, *p_conved, *p_comb, *p_cbias;
    bf16 *p_wt_h, *p_wt_l, *p_weh_h, *p_weh_l, *p_whe_h, *p_whe_l;
    bf16 *p_wahe_h, *p_wahe_l, *p_waeh_h, *p_waeh_l, *p_wfc_h, *p_wfc_l;
    bf16 *p_xpad_h, *p_xpad_l, *p_emb_h, *p_emb_l, *p_conved_h, *p_conved_l;
    bf16 *p_attenc_h, *p_attenc_l, *p_comb_h, *p_comb_l;
    cudaGetSymbolAddress((void**)&p_xpad, g_xpad);
    cudaGetSymbolAddress((void**)&p_emb, g_emb);
    cudaGetSymbolAddress((void**)&p_conved, g_conved);
    cudaGetSymbolAddress((void**)&p_comb, g_comb);
    cudaGetSymbolAddress((void**)&p_cbias, g_cbias);
    cudaGetSymbolAddress((void**)&p_wt_h, g_wt_h);   cudaGetSymbolAddress((void**)&p_wt_l, g_wt_l);
    cudaGetSymbolAddress((void**)&p_weh_h, g_weh_h); cudaGetSymbolAddress((void**)&p_weh_l, g_weh_l);
    cudaGetSymbolAddress((void**)&p_whe_h, g_whe_h); cudaGetSymbolAddress((void**)&p_whe_l, g_whe_l);
    cudaGetSymbolAddress((void**)&p_wahe_h, g_wahe_h); cudaGetSymbolAddress((void**)&p_wahe_l, g_wahe_l);
    cudaGetSymbolAddress((void**)&p_waeh_h, g_waeh_h); cudaGetSymbolAddress((void**)&p_waeh_l, g_waeh_l);
    cudaGetSymbolAddress((void**)&p_wfc_h, g_wfc_h); cudaGetSymbolAddress((void**)&p_wfc_l, g_wfc_l);
    cudaGetSymbolAddress((void**)&p_xpad_h, g_xpad_h); cudaGetSymbolAddress((void**)&p_xpad_l, g_xpad_l);
    cudaGetSymbolAddress((void**)&p_emb_h, g_emb_h); cudaGetSymbolAddress((void**)&p_emb_l, g_emb_l);
    cudaGetSymbolAddress((void**)&p_conved_h, g_conved_h); cudaGetSymbolAddress((void**)&p_conved_l, g_conved_l);
    cudaGetSymbolAddress((void**)&p_attenc_h, g_attenc_h); cudaGetSymbolAddress((void**)&p_attenc_l, g_attenc_l);
    cudaGetSymbolAddress((void**)&p_comb_h, g_comb_h); cudaGetSymbolAddress((void**)&p_comb_l, g_comb_l);

    const float SC = 0.7071067811865476f;

    // launch 1: ALL weight prep
    k_prep<<<(unsigned)((PREP_TOTAL + 255) / 256), 256>>>(
        conv_w, conv_b, w_eh, w_he, w_ahe, w_aeh, w_fc);
    // launch 2: embed + zero pad
    k_embed<<<(MM*EE + BB*2*HH + 255) / 256, 256>>>(target, src_emb, pos_emb);

    // launch 3: conv_input = embedded @ w_eh^T + b_eh (fp32 + fused hi/lo)
    launch_tc(p_emb_h, p_emb_l, 0, EE, p_weh_h, p_weh_l, b_eh, nullptr, 0, 1.f,
              p_xpad, p_xpad_h, p_xpad_l, 1, HH, MM, HH, EE);

    for (int l = 0; l < LL; l++) {
        const size_t wo = (size_t)l*2*HH*3*HH;
        // launch 4 (l=0): conv + fused GLU   <- target of ncu -s 5 -c 1
        launch_tc(p_xpad_h, p_xpad_l, 2, HH, p_wt_h + wo, p_wt_l + wo,
                  p_cbias + (size_t)l*2*HH, nullptr, 0, 1.f,
                  p_conved, p_conved_h, p_conved_l, 0, HH, MM, 2*HH, 3*HH, 1);
        // comb = (conved @ w_ahe^T + b_ahe + embedded) * sqrt(.5)
        launch_tc(p_conved_h, p_conved_l, 0, HH, p_wahe_h, p_wahe_l,
                  b_ahe, p_emb, EE, SC, p_comb, nullptr, nullptr, 0, EE, MM, EE, HH);
        // fused energy + softmax + att_enc (+split)
        k_att<<<MM/32, 256>>>(encC, encComb);
        // conved = (att_enc @ w_aeh^T + b_aeh + conved)*SC; xpad = (conved + xpad)*SC
        launch_tc(p_attenc_h, p_attenc_l, 0, EE, p_waeh_h, p_waeh_l,
                  b_aeh, p_conved, HH, SC, p_conved, p_conved_h, p_conved_l,
                  0, HH, MM, HH, EE, 2, p_xpad, p_xpad_h, p_xpad_l);
    }

    // hidden = conv_input @ w_he^T + b_he (fp32 + fused hi/lo)
    launch_tc(p_xpad_h, p_xpad_l, 1, HH, p_whe_h, p_whe_l, b_he, nullptr, 0, 1.f,
              p_comb, p_comb_h, p_comb_l, 0, EE, MM, EE, HH);
    // logits = hidden @ w_fc^T + b_fc -> d_out
    launch_tc(p_comb_h, p_comb_l, 0, EE, p_wfc_h, p_wfc_l, b_fc, nullptr, 0, 1.f,
              out, nullptr, nullptr, 0, VV, MM, VV, EE);

    // attention (last layer) appended after logits
    const long long ATT_OFF = (long long)MM * VV;
    if ((long long)out_size >= ATT_OFF + (long long)MM*SS) {
        k_attcopy<<<(MM*SS + 255) / 256, 256>>>(out + ATT_OFF);
    }
}